// round 11
// baseline (speedup 1.0000x reference)
#include <cuda_runtime.h>
#include <cuda_bf16.h>
#include <cstdint>

#define LDD 192
#define M_TOTAL 64000
#define AB_STRIDE ((size_t)M_TOTAL * LDD)
#define GSTRIDE (LDD * LDD)

// ---------------- scratch (static device globals; keep total well under ~256 MB) ----------------
static __device__ float g_B[3 * AB_STRIDE];   // ~147 MB (branch-batched)
static __device__ float g_A[AB_STRIDE];       // ~49 MB (shared, per-branch reuse)
static __device__ float g_G[3 * GSTRIDE];
static __device__ float g_T[3 * GSTRIDE];
static __device__ float g_Pt[3 * GSTRIDE];
static __device__ float g_Wp[3 * GSTRIDE];

// ---------------- per-branch compile-time traits ----------------
template<int BR> struct Tr;
template<> struct Tr<0> { // axi: s=(48,66,38) w=(5,7,4) d=140 pb=(1,2,1)
  static constexpr int w0=5,w1=7,w2=4,d=140,nt=3;
  static constexpr int s0=48,s1=66,s2=38;
  static constexpr int pb0=1,pb1=2,pb2=1;
  static constexpr long OFF=0;
};
template<> struct Tr<1> { // cor (internal transpose 0,1,2,4,3): s=(38,38,66) w=(4,4,7) d=112 pb=(1,1,2)
  static constexpr int w0=4,w1=4,w2=7,d=112,nt=2;
  static constexpr int s0=38,s1=38,s2=66;
  static constexpr int pb0=1,pb1=1,pb2=2;
  static constexpr long OFF=7704576;
};
template<> struct Tr<2> { // sag (internal transpose 0,1,4,3,2): s=(38,78,48) w=(4,8,5) d=160 pb=(1,1,1)
  static constexpr int w0=4,w1=8,w2=5,d=160,nt=3;
  static constexpr int s0=38,s1=78,s2=48;
  static constexpr int pb0=1,pb1=1,pb2=1;
  static constexpr long OFF=13804032;
};

template<int BR>
__device__ __forceinline__ void amap(int x, int y, int z, int& xb, int& yb, int& zb) {
  if (BR == 0) {
    xb = x; yb = (y * 6) / 7; zb = z;
  } else if (BR == 1) {
    int x2 = (x * 5) / 4, y2 = (y * 7) / 4, z2 = (z * 4) / 7;
    xb = x2; yb = (y2 * 6) / 7; zb = z2;
  } else {
    int y3 = y / 2, z3 = (z * 7) / 5;
    int x2 = (x * 5) / 4, y2 = (y3 * 7) / 4, z2 = (z3 * 4) / 7;
    xb = x2; yb = (y2 * 6) / 7; zb = z2;
  }
}

// ---------------- packB: gather B-hat for all branches in one launch ----------------
template<int BR>
__device__ void packB_body(const float* __restrict__ feat) {
  constexpr int w0=Tr<BR>::w0, w1=Tr<BR>::w1, w2=Tr<BR>::w2, d=Tr<BR>::d;
  constexpr int s0=Tr<BR>::s0, s1=Tr<BR>::s1, s2=Tr<BR>::s2;
  constexpr int pb0=Tr<BR>::pb0, pb1=Tr<BR>::pb1, pb2=Tr<BR>::pb2;
  float* Bdst = g_B + (size_t)BR * AB_STRIDE;
  int blk = blockIdx.x;
  int c = blk / 100;
  int a = (blk / 10) % 10;
  int b = blk % 10;
  for (int t = threadIdx.x; t < 10 * LDD; t += blockDim.x) {
    int cc = t / LDD;
    int j  = t - cc * LDD;
    int row = blk * 10 + cc;
    float vB;
    if (j < d) {
      int x = j / (w1 * w2);
      int y = (j / w2) % w1;
      int z = j % w2;
      int i0 = a * w0 + x - pb0;
      int i1 = b * w1 + y - pb1;
      int i2 = cc * w2 + z - pb2;
      vB = 0.f;
      if ((unsigned)i0 < (unsigned)s0 && (unsigned)i1 < (unsigned)s1 && (unsigned)i2 < (unsigned)s2) {
        int src;
        if (BR == 0)      src = ((c * 48 + i0) * 66 + i1) * 38 + i2;
        else if (BR == 1) src = ((c * 38 + i0) * 66 + i2) * 38 + i1;
        else              src = ((c * 48 + i2) * 78 + i1) * 38 + i0;
        vB = feat[src];
      }
    } else {
      vB = (j == d) ? 1.f : 0.f;
    }
    Bdst[(size_t)row * LDD + j] = vB;
  }
}

__global__ void packB_all(const float* __restrict__ axi, const float* __restrict__ cor,
                          const float* __restrict__ sag) {
  if (blockIdx.y == 0)      packB_body<0>(axi);
  else if (blockIdx.y == 1) packB_body<1>(cor);
  else                      packB_body<2>(sag);
}

// ---------------- packA: gather A-hat for one branch into shared buffer ----------------
template<int BR>
__global__ void packA_kernel(const float* __restrict__ atlas) {
  constexpr int w1=Tr<BR>::w1, w2=Tr<BR>::w2, d=Tr<BR>::d;
  int blk = blockIdx.x;
  int a = (blk / 10) % 10;
  int b = blk % 10;
  int c = blk / 100;
  for (int t = threadIdx.x; t < 10 * LDD; t += blockDim.x) {
    int cc = t / LDD;
    int j  = t - cc * LDD;
    int row = blk * 10 + cc;
    float vA;
    if (j < d) {
      int x = j / (w1 * w2);
      int y = (j / w2) % w1;
      int z = j % w2;
      int xb, yb, zb;
      amap<BR>(x, y, z, xb, yb, zb);
      int j0 = a * 5 + xb - 2;   // atlas aw=(5,6,4), pb=(2,2,1)
      int j1 = b * 6 + yb - 2;
      int j2 = cc * 4 + zb - 1;
      vA = 0.f;
      if ((unsigned)j0 < 46u && (unsigned)j1 < 56u && (unsigned)j2 < 38u)
        vA = atlas[((c * 46 + j0) * 56 + j1) * 38 + j2];
    } else {
      vA = (j == d) ? 1.f : 0.f;
    }
    g_A[(size_t)row * LDD + j] = vA;
  }
}

__global__ void zero_all() {
  int i = blockIdx.x * blockDim.x + threadIdx.x;
  if (i < 3 * GSTRIDE) { g_G[i] = 0.f; g_Wp[i] = 0.f; }
}

// ---------------- GEMM1: G = A-hat^T * B-hat, one branch, split-M, 8x8 micro ----------------
template<int BR>
__global__ void __launch_bounds__(64, 8) gemm1_kernel(int mChunk) {
  int p0 = blockIdx.x * 64;
  int q0 = blockIdx.y * 64;
  int m0 = blockIdx.z * mChunk;
  int mHi = min(m0 + mChunk, M_TOTAL);
  if (m0 >= mHi) return;
  const float* A  = g_A;
  const float* Bp = g_B + (size_t)BR * AB_STRIDE;
  float* G = g_G + BR * GSTRIDE;
  __shared__ alignas(16) float As[16][64];
  __shared__ alignas(16) float Bs[16][64];
  float acc[8][8] = {};
  int t = threadIdx.x;               // 64 threads
  int tx = t & 7, ty = t >> 3;
  int lr = t >> 4, lc = (t & 15) * 4;
  float4 pa[4], pb[4];
#define G1_LD(MB)                                                        \
  {                                                                      \
    _Pragma("unroll")                                                    \
    for (int i = 0; i < 4; i++) {                                        \
      int row = (MB) + lr + i * 4;                                       \
      if (row < mHi) {                                                   \
        pa[i] = *(const float4*)(A  + (size_t)row * LDD + p0 + lc);      \
        pb[i] = *(const float4*)(Bp + (size_t)row * LDD + q0 + lc);      \
      } else { pa[i] = make_float4(0.f,0.f,0.f,0.f); pb[i] = pa[i]; }    \
    }                                                                    \
  }
  G1_LD(m0);
  for (int mb = m0; mb < mHi; mb += 16) {
    __syncthreads();
#pragma unroll
    for (int i = 0; i < 4; i++) {
      *(float4*)&As[lr + i * 4][lc] = pa[i];
      *(float4*)&Bs[lr + i * 4][lc] = pb[i];
    }
    __syncthreads();
    if (mb + 16 < mHi) G1_LD(mb + 16);
#pragma unroll
    for (int k = 0; k < 16; k++) {
      float a[8], b[8];
      *(float4*)&a[0] = *(float4*)&As[k][ty * 8];
      *(float4*)&a[4] = *(float4*)&As[k][ty * 8 + 4];
      *(float4*)&b[0] = *(float4*)&Bs[k][tx * 8];
      *(float4*)&b[4] = *(float4*)&Bs[k][tx * 8 + 4];
#pragma unroll
      for (int i = 0; i < 8; i++)
#pragma unroll
        for (int j = 0; j < 8; j++)
          acc[i][j] += a[i] * b[j];
    }
  }
#pragma unroll
  for (int i = 0; i < 8; i++)
#pragma unroll
    for (int j = 0; j < 8; j++)
      atomicAdd(&G[(p0 + ty * 8 + i) * LDD + q0 + tx * 8 + j], acc[i][j]);
#undef G1_LD
}

// ---------------- small chain (batched across branches) ----------------
struct P3 { const float* W0; const float* b0; const float* W1; const float* b1;
            const float* W2; const float* b2; };

__device__ __forceinline__ void sel(const P3& p, int br, const float*& W, const float*& b) {
  if (br == 0)      { W = p.W0; b = p.b0; }
  else if (br == 1) { W = p.W1; b = p.b1; }
  else              { W = p.W2; b = p.b2; }
}

// T = G-hat @ Wk-hat
__global__ void k3a_all(P3 pk) {
  const int dTab[3] = {140, 112, 160};
  int br = blockIdx.x / 161;
  int r  = blockIdx.x - br * 161;
  int d = dTab[br];
  if (r > d) return;
  const float *Wk, *bk; sel(pk, br, Wk, bk);
  const float* G = g_G + br * GSTRIDE;
  float* T = g_T + br * GSTRIDE;
  __shared__ float gsh[192];
  int t = threadIdx.x;               // 192
  gsh[t] = (t <= d) ? G[r * LDD + t] : 0.f;
  __syncthreads();
  if (t < d) {
    float s = gsh[d] * bk[t];
#pragma unroll 4
    for (int ss = 0; ss < d; ss++) s += gsh[ss] * Wk[ss * d + t];
    T[r * LDD + t] = s;
  }
}

// S row p = Wq-hat[:,p]^T @ T, fused softmax, write P transposed
__global__ void k3b_all(P3 pq) {
  const int dTab[3] = {140, 112, 160};
  int br = blockIdx.x / 160;
  int p  = blockIdx.x - br * 160;
  int d = dTab[br];
  if (p >= d) return;
  const float *Wq, *bq; sel(pq, br, Wq, bq);
  const float* T = g_T + br * GSTRIDE;
  float* Pt = g_Pt + br * GSTRIDE;
  __shared__ float wq[192];
  __shared__ float red[256];
  int t = threadIdx.x;               // 256
  int D = d + 1;
  if (t < 192) wq[t] = (t < d) ? Wq[t * d + p] : ((t == d) ? bq[p] : 0.f);
  __syncthreads();
  float s = -3.0e38f;
  if (t < d) {
    s = 0.f;
#pragma unroll 4
    for (int r = 0; r < D; r++) s += wq[r] * T[r * LDD + t];
  }
  red[t] = s; __syncthreads();
  for (int o = 128; o > 0; o >>= 1) { if (t < o) red[t] = fmaxf(red[t], red[t + o]); __syncthreads(); }
  float mx = red[0]; __syncthreads();
  float e = (t < d) ? expf(s - mx) : 0.f;
  red[t] = e; __syncthreads();
  for (int o = 128; o > 0; o >>= 1) { if (t < o) red[t] += red[t + o]; __syncthreads(); }
  float inv = 1.f / red[0];
  if (t < d) Pt[t * LDD + p] = e * inv;
}

// W' row j = Wv-hat[j,:] @ P^T
__global__ void k3d_all(P3 pv) {
  const int dTab[3] = {140, 112, 160};
  int br = blockIdx.x / 161;
  int j  = blockIdx.x - br * 161;
  int d = dTab[br];
  if (j > d) return;
  const float *Wv, *bv; sel(pv, br, Wv, bv);
  const float* Pt = g_Pt + br * GSTRIDE;
  float* Wp = g_Wp + br * GSTRIDE;
  __shared__ float wv[192];
  int t = threadIdx.x;               // 192
  if (t < d) wv[t] = (j < d) ? Wv[j * d + t] : bv[t];
  __syncthreads();
  if (t < d) {
    float s = 0.f;
#pragma unroll 4
    for (int l = 0; l < d; l++) s += wv[l] * Pt[l * LDD + t];
    Wp[j * LDD + t] = s;
  }
}

// ================= GEMM2 via mma.sync bf16, 2-way split (K-interleaved) =================
// D[128x64] = Bhat[128x192] @ Wp[192x64]
// split: D = Ah*Bh + Ah*Bl + Al*Bh, fp32 accum, virtual K = 3*192 = 576 (36 chunks of 16)
// A smem: 128 rows x [Ah(192) | Al(192)] stride 392 bf16 (196 words == 4 mod 32: conflict-free)
// B smem: 64 rows  x [Bh(192) | Bl(192) | Bh(192)] stride 584 bf16 (292 words == 4 mod 32)

#define G2_SA 392
#define G2_SB 584
#define G2_BOFF (128 * G2_SA)                       // B plane offset in bf16 elems
#define G2_SMEM ((G2_BOFF + 64 * G2_SB) * 2)        // 175104 bytes

__device__ __forceinline__ void hmma16816(float* c, const uint32_t* a, uint32_t b0, uint32_t b1) {
  asm volatile(
      "mma.sync.aligned.m16n8k16.row.col.f32.bf16.bf16.f32 "
      "{%0,%1,%2,%3}, {%4,%5,%6,%7}, {%8,%9}, {%0,%1,%2,%3};"
      : "+f"(c[0]), "+f"(c[1]), "+f"(c[2]), "+f"(c[3])
      : "r"(a[0]), "r"(a[1]), "r"(a[2]), "r"(a[3]), "r"(b0), "r"(b1));
}

template<int BR>
__global__ void __launch_bounds__(256, 1) gemm2_hmma(float* __restrict__ out) {
  constexpr int d  = Tr<BR>::d;
  constexpr int w0 = Tr<BR>::w0, w1 = Tr<BR>::w1, w2 = Tr<BR>::w2;
  constexpr int s0 = Tr<BR>::s0, s1 = Tr<BR>::s1, s2 = Tr<BR>::s2;
  constexpr int pb0 = Tr<BR>::pb0, pb1 = Tr<BR>::pb1, pb2 = Tr<BR>::pb2;
  extern __shared__ __nv_bfloat16 smh[];
  __nv_bfloat16* Asm = smh;
  __nv_bfloat16* Bsm = smh + G2_BOFF;
  int t = threadIdx.x;
  int m0 = blockIdx.x * 128, n0 = blockIdx.y * 64;
  const float* Bg = g_B + (size_t)BR * AB_STRIDE;
  const float* Wp = g_Wp + BR * GSTRIDE;

  // ---- fill A planes: rows m0..m0+127, k 0..191, hi/lo split ----
  for (int i = t; i < 128 * 192; i += 256) {
    int row = i / 192, col = i - row * 192;
    float x = Bg[(size_t)(m0 + row) * LDD + col];
    __nv_bfloat16 h = __float2bfloat16(x);
    __nv_bfloat16 l = __float2bfloat16(x - __bfloat162float(h));
    Asm[row * G2_SA + col]       = h;
    Asm[row * G2_SA + 192 + col] = l;
  }
  // ---- fill B planes: Bmat[n][k] = Wp[k][n0+n] ----
  for (int i = t; i < 64 * 192; i += 256) {
    int n = i / 192, k = i - n * 192;
    float x = Wp[k * LDD + n0 + n];
    __nv_bfloat16 h = __float2bfloat16(x);
    __nv_bfloat16 l = __float2bfloat16(x - __bfloat162float(h));
    Bsm[n * G2_SB + k]       = h;
    Bsm[n * G2_SB + 192 + k] = l;
    Bsm[n * G2_SB + 384 + k] = h;
  }
  __syncthreads();

  // ---- warp tiling: 8 warps = 4(m) x 2(n); warp tile 32(m) x 32(n) ----
  int wid = t >> 5, lane = t & 31;
  int wm = wid & 3, wn = wid >> 2;
  int g = lane >> 2, c4 = lane & 3;
  float acc[2][4][4] = {};

  for (int ch = 0; ch < 36; ch++) {
    int aoff = (ch < 12) ? ch * 16 : (ch < 24 ? (ch - 12) * 16 : 192 + (ch - 24) * 16);
    int boff = (ch < 12) ? ch * 16 : (ch < 24 ? 192 + (ch - 12) * 16 : 384 + (ch - 24) * 16);
    uint32_t a[2][4];
#pragma unroll
    for (int mt = 0; mt < 2; mt++) {
      int r0 = wm * 32 + mt * 16 + g;
      a[mt][0] = *(const uint32_t*)&Asm[r0 * G2_SA + aoff + c4 * 2];
      a[mt][1] = *(const uint32_t*)&Asm[(r0 + 8) * G2_SA + aoff + c4 * 2];
      a[mt][2] = *(const uint32_t*)&Asm[r0 * G2_SA + aoff + 8 + c4 * 2];
      a[mt][3] = *(const uint32_t*)&Asm[(r0 + 8) * G2_SA + aoff + 8 + c4 * 2];
    }
#pragma unroll
    for (int nt = 0; nt < 4; nt++) {
      int nr = wn * 32 + nt * 8 + g;
      uint32_t b0 = *(const uint32_t*)&Bsm[nr * G2_SB + boff + c4 * 2];
      uint32_t b1 = *(const uint32_t*)&Bsm[nr * G2_SB + boff + 8 + c4 * 2];
      hmma16816(acc[0][nt], a[0], b0, b1);
      hmma16816(acc[1][nt], a[1], b0, b1);
    }
  }

  // ---- scatter epilogue: fold + crop + branch transpose ----
#pragma unroll
  for (int mt = 0; mt < 2; mt++) {
#pragma unroll
    for (int hh = 0; hh < 2; hh++) {      // hh=0: row g, hh=1: row g+8 (acc idx 2,3)
      int m = m0 + wm * 32 + mt * 16 + g + hh * 8;
      int chn = m / 1000;
      int rem = m - chn * 1000;
      int ra  = (rem / 100) * w0 - pb0;
      int rb  = ((rem / 10) % 10) * w1 - pb1;
      int rcc = (rem % 10) * w2 - pb2;
#pragma unroll
      for (int nt = 0; nt < 4; nt++) {
#pragma unroll
        for (int e = 0; e < 2; e++) {
          int col = n0 + wn * 32 + nt * 8 + c4 * 2 + e;
          float val = acc[mt][nt][hh * 2 + e];
          if (col < d) {
            int x = col / (w1 * w2);
            int y = (col / w2) % w1;
            int z = col % w2;
            int u0 = ra + x, u1 = rb + y, u2 = rcc + z;
            if ((unsigned)u0 < (unsigned)s0 && (unsigned)u1 < (unsigned)s1 && (unsigned)u2 < (unsigned)s2) {
              long dst;
              if (BR == 0)      dst = ((long)(chn * 48 + u0) * 66 + u1) * 38 + u2;
              else if (BR == 1) dst = ((long)(chn * 38 + u0) * 66 + u2) * 38 + u1;
              else              dst = ((long)(chn * 48 + u2) * 78 + u1) * 38 + u0;
              out[Tr<BR>::OFF + dst] = val;
            }
          }
        }
      }
    }
  }
}

// ---------------- host driver ----------------
extern "C" void kernel_launch(void* const* d_in, const int* in_sizes, int n_in,
                              void* d_out, int out_size) {
  const float* axi   = (const float*)d_in[0];
  const float* cor   = (const float*)d_in[1];
  const float* sag   = (const float*)d_in[2];
  const float* atlas = (const float*)d_in[3];
  float* out = (float*)d_out;

  P3 pq = { (const float*)d_in[4],  (const float*)d_in[5],
            (const float*)d_in[10], (const float*)d_in[11],
            (const float*)d_in[16], (const float*)d_in[17] };
  P3 pk = { (const float*)d_in[6],  (const float*)d_in[7],
            (const float*)d_in[12], (const float*)d_in[13],
            (const float*)d_in[18], (const float*)d_in[19] };
  P3 pv = { (const float*)d_in[8],  (const float*)d_in[9],
            (const float*)d_in[14], (const float*)d_in[15],
            (const float*)d_in[20], (const float*)d_in[21] };

  cudaFuncSetAttribute(gemm2_hmma<0>, cudaFuncAttributeMaxDynamicSharedMemorySize, G2_SMEM);
  cudaFuncSetAttribute(gemm2_hmma<1>, cudaFuncAttributeMaxDynamicSharedMemorySize, G2_SMEM);
  cudaFuncSetAttribute(gemm2_hmma<2>, cudaFuncAttributeMaxDynamicSharedMemorySize, G2_SMEM);

  // split-M factors tuned for ~8 blocks/SM (148 SMs, 64-thread blocks)
  const int NS0 = 128, CH0 = (M_TOTAL + NS0 - 1) / NS0;
  const int NS1 = 288, CH1 = (M_TOTAL + NS1 - 1) / NS1;
  const int NS2 = 128, CH2 = (M_TOTAL + NS2 - 1) / NS2;

  zero_all<<<(3 * GSTRIDE + 255) / 256, 256>>>();
  packB_all<<<dim3(6400, 3), 256>>>(axi, cor, sag);

  packA_kernel<0><<<6400, 256>>>(atlas);
  gemm1_kernel<0><<<dim3(3, 3, NS0), 64>>>(CH0);
  packA_kernel<1><<<6400, 256>>>(atlas);
  gemm1_kernel<1><<<dim3(2, 2, NS1), 64>>>(CH1);
  packA_kernel<2><<<6400, 256>>>(atlas);
  gemm1_kernel<2><<<dim3(3, 3, NS2), 64>>>(CH2);

  k3a_all<<<3 * 161, 192>>>(pk);
  k3b_all<<<3 * 160, 256>>>(pq);
  k3d_all<<<3 * 161, 192>>>(pv);

  gemm2_hmma<0><<<dim3(500, 3), 256, G2_SMEM>>>(out);
  gemm2_hmma<1><<<dim3(500, 2), 256, G2_SMEM>>>(out);
  gemm2_hmma<2><<<dim3(500, 3), 256, G2_SMEM>>>(out);
}

// round 12
// speedup vs baseline: 1.0276x; 1.0276x over previous
#include <cuda_runtime.h>
#include <cuda_bf16.h>
#include <cstdint>

#define LDD 192
#define M_TOTAL 64000
#define AB_STRIDE ((size_t)M_TOTAL * LDD)
#define GSTRIDE (LDD * LDD)

// ---------------- scratch (static device globals; keep total well under ~256 MB) ----------------
static __device__ float g_B[3 * AB_STRIDE];   // ~147 MB (branch-batched)
static __device__ float g_A[AB_STRIDE];       // ~49 MB (shared, per-branch reuse)
static __device__ float g_G[3 * GSTRIDE];
static __device__ float g_T[3 * GSTRIDE];
static __device__ float g_Pt[3 * GSTRIDE];
static __device__ float g_Wp[3 * GSTRIDE];

// ---------------- per-branch compile-time traits ----------------
template<int BR> struct Tr;
template<> struct Tr<0> { // axi: s=(48,66,38) w=(5,7,4) d=140 pb=(1,2,1)
  static constexpr int w0=5,w1=7,w2=4,d=140,nt=3;
  static constexpr int s0=48,s1=66,s2=38;
  static constexpr int pb0=1,pb1=2,pb2=1;
  static constexpr long OFF=0;
};
template<> struct Tr<1> { // cor (internal transpose 0,1,2,4,3): s=(38,38,66) w=(4,4,7) d=112 pb=(1,1,2)
  static constexpr int w0=4,w1=4,w2=7,d=112,nt=2;
  static constexpr int s0=38,s1=38,s2=66;
  static constexpr int pb0=1,pb1=1,pb2=2;
  static constexpr long OFF=7704576;
};
template<> struct Tr<2> { // sag (internal transpose 0,1,4,3,2): s=(38,78,48) w=(4,8,5) d=160 pb=(1,1,1)
  static constexpr int w0=4,w1=8,w2=5,d=160,nt=3;
  static constexpr int s0=38,s1=78,s2=48;
  static constexpr int pb0=1,pb1=1,pb2=1;
  static constexpr long OFF=13804032;
};

template<int BR>
__device__ __forceinline__ void amap(int x, int y, int z, int& xb, int& yb, int& zb) {
  if (BR == 0) {
    xb = x; yb = (y * 6) / 7; zb = z;
  } else if (BR == 1) {
    int x2 = (x * 5) / 4, y2 = (y * 7) / 4, z2 = (z * 4) / 7;
    xb = x2; yb = (y2 * 6) / 7; zb = z2;
  } else {
    int y3 = y / 2, z3 = (z * 7) / 5;
    int x2 = (x * 5) / 4, y2 = (y3 * 7) / 4, z2 = (z3 * 4) / 7;
    xb = x2; yb = (y2 * 6) / 7; zb = z2;
  }
}

// ---------------- packB: gather B-hat for all branches in one launch ----------------
template<int BR>
__device__ void packB_body(const float* __restrict__ feat) {
  constexpr int w0=Tr<BR>::w0, w1=Tr<BR>::w1, w2=Tr<BR>::w2, d=Tr<BR>::d;
  constexpr int s0=Tr<BR>::s0, s1=Tr<BR>::s1, s2=Tr<BR>::s2;
  constexpr int pb0=Tr<BR>::pb0, pb1=Tr<BR>::pb1, pb2=Tr<BR>::pb2;
  float* Bdst = g_B + (size_t)BR * AB_STRIDE;
  int blk = blockIdx.x;
  int c = blk / 100;
  int a = (blk / 10) % 10;
  int b = blk % 10;
  for (int t = threadIdx.x; t < 10 * LDD; t += blockDim.x) {
    int cc = t / LDD;
    int j  = t - cc * LDD;
    int row = blk * 10 + cc;
    float vB;
    if (j < d) {
      int x = j / (w1 * w2);
      int y = (j / w2) % w1;
      int z = j % w2;
      int i0 = a * w0 + x - pb0;
      int i1 = b * w1 + y - pb1;
      int i2 = cc * w2 + z - pb2;
      vB = 0.f;
      if ((unsigned)i0 < (unsigned)s0 && (unsigned)i1 < (unsigned)s1 && (unsigned)i2 < (unsigned)s2) {
        int src;
        if (BR == 0)      src = ((c * 48 + i0) * 66 + i1) * 38 + i2;
        else if (BR == 1) src = ((c * 38 + i0) * 66 + i2) * 38 + i1;
        else              src = ((c * 48 + i2) * 78 + i1) * 38 + i0;
        vB = feat[src];
      }
    } else {
      vB = (j == d) ? 1.f : 0.f;
    }
    Bdst[(size_t)row * LDD + j] = vB;
  }
}

__global__ void packB_all(const float* __restrict__ axi, const float* __restrict__ cor,
                          const float* __restrict__ sag) {
  if (blockIdx.y == 0)      packB_body<0>(axi);
  else if (blockIdx.y == 1) packB_body<1>(cor);
  else                      packB_body<2>(sag);
}

// ---------------- packA: gather A-hat for one branch into shared buffer ----------------
template<int BR>
__global__ void packA_kernel(const float* __restrict__ atlas) {
  constexpr int w1=Tr<BR>::w1, w2=Tr<BR>::w2, d=Tr<BR>::d;
  int blk = blockIdx.x;
  int a = (blk / 10) % 10;
  int b = blk % 10;
  int c = blk / 100;
  for (int t = threadIdx.x; t < 10 * LDD; t += blockDim.x) {
    int cc = t / LDD;
    int j  = t - cc * LDD;
    int row = blk * 10 + cc;
    float vA;
    if (j < d) {
      int x = j / (w1 * w2);
      int y = (j / w2) % w1;
      int z = j % w2;
      int xb, yb, zb;
      amap<BR>(x, y, z, xb, yb, zb);
      int j0 = a * 5 + xb - 2;   // atlas aw=(5,6,4), pb=(2,2,1)
      int j1 = b * 6 + yb - 2;
      int j2 = cc * 4 + zb - 1;
      vA = 0.f;
      if ((unsigned)j0 < 46u && (unsigned)j1 < 56u && (unsigned)j2 < 38u)
        vA = atlas[((c * 46 + j0) * 56 + j1) * 38 + j2];
    } else {
      vA = (j == d) ? 1.f : 0.f;
    }
    g_A[(size_t)row * LDD + j] = vA;
  }
}

__global__ void zero_all() {
  int i = blockIdx.x * blockDim.x + threadIdx.x;
  if (i < 3 * GSTRIDE) { g_G[i] = 0.f; g_Wp[i] = 0.f; }
}

// ---------------- GEMM1: G = A-hat^T * B-hat, one branch, split-M, 8x8 micro ----------------
template<int BR>
__global__ void __launch_bounds__(64, 8) gemm1_kernel(int mChunk) {
  int p0 = blockIdx.x * 64;
  int q0 = blockIdx.y * 64;
  int m0 = blockIdx.z * mChunk;
  int mHi = min(m0 + mChunk, M_TOTAL);
  if (m0 >= mHi) return;
  const float* A  = g_A;
  const float* Bp = g_B + (size_t)BR * AB_STRIDE;
  float* G = g_G + BR * GSTRIDE;
  __shared__ alignas(16) float As[16][64];
  __shared__ alignas(16) float Bs[16][64];
  float acc[8][8] = {};
  int t = threadIdx.x;               // 64 threads
  int tx = t & 7, ty = t >> 3;
  int lr = t >> 4, lc = (t & 15) * 4;
  float4 pa[4], pb[4];
#define G1_LD(MB)                                                        \
  {                                                                      \
    _Pragma("unroll")                                                    \
    for (int i = 0; i < 4; i++) {                                        \
      int row = (MB) + lr + i * 4;                                       \
      if (row < mHi) {                                                   \
        pa[i] = *(const float4*)(A  + (size_t)row * LDD + p0 + lc);      \
        pb[i] = *(const float4*)(Bp + (size_t)row * LDD + q0 + lc);      \
      } else { pa[i] = make_float4(0.f,0.f,0.f,0.f); pb[i] = pa[i]; }    \
    }                                                                    \
  }
  G1_LD(m0);
  for (int mb = m0; mb < mHi; mb += 16) {
    __syncthreads();
#pragma unroll
    for (int i = 0; i < 4; i++) {
      *(float4*)&As[lr + i * 4][lc] = pa[i];
      *(float4*)&Bs[lr + i * 4][lc] = pb[i];
    }
    __syncthreads();
    if (mb + 16 < mHi) G1_LD(mb + 16);
#pragma unroll
    for (int k = 0; k < 16; k++) {
      float a[8], b[8];
      *(float4*)&a[0] = *(float4*)&As[k][ty * 8];
      *(float4*)&a[4] = *(float4*)&As[k][ty * 8 + 4];
      *(float4*)&b[0] = *(float4*)&Bs[k][tx * 8];
      *(float4*)&b[4] = *(float4*)&Bs[k][tx * 8 + 4];
#pragma unroll
      for (int i = 0; i < 8; i++)
#pragma unroll
        for (int j = 0; j < 8; j++)
          acc[i][j] += a[i] * b[j];
    }
  }
#pragma unroll
  for (int i = 0; i < 8; i++)
#pragma unroll
    for (int j = 0; j < 8; j++)
      atomicAdd(&G[(p0 + ty * 8 + i) * LDD + q0 + tx * 8 + j], acc[i][j]);
#undef G1_LD
}

// ---------------- small chain (batched across branches) ----------------
struct P3 { const float* W0; const float* b0; const float* W1; const float* b1;
            const float* W2; const float* b2; };

__device__ __forceinline__ void sel(const P3& p, int br, const float*& W, const float*& b) {
  if (br == 0)      { W = p.W0; b = p.b0; }
  else if (br == 1) { W = p.W1; b = p.b1; }
  else              { W = p.W2; b = p.b2; }
}

// T = G-hat @ Wk-hat
__global__ void k3a_all(P3 pk) {
  const int dTab[3] = {140, 112, 160};
  int br = blockIdx.x / 161;
  int r  = blockIdx.x - br * 161;
  int d = dTab[br];
  if (r > d) return;
  const float *Wk, *bk; sel(pk, br, Wk, bk);
  const float* G = g_G + br * GSTRIDE;
  float* T = g_T + br * GSTRIDE;
  __shared__ float gsh[192];
  int t = threadIdx.x;               // 192
  gsh[t] = (t <= d) ? G[r * LDD + t] : 0.f;
  __syncthreads();
  if (t < d) {
    float s = gsh[d] * bk[t];
#pragma unroll 4
    for (int ss = 0; ss < d; ss++) s += gsh[ss] * Wk[ss * d + t];
    T[r * LDD + t] = s;
  }
}

// S row p = Wq-hat[:,p]^T @ T, fused softmax, write P transposed
__global__ void k3b_all(P3 pq) {
  const int dTab[3] = {140, 112, 160};
  int br = blockIdx.x / 160;
  int p  = blockIdx.x - br * 160;
  int d = dTab[br];
  if (p >= d) return;
  const float *Wq, *bq; sel(pq, br, Wq, bq);
  const float* T = g_T + br * GSTRIDE;
  float* Pt = g_Pt + br * GSTRIDE;
  __shared__ float wq[192];
  __shared__ float red[256];
  int t = threadIdx.x;               // 256
  int D = d + 1;
  if (t < 192) wq[t] = (t < d) ? Wq[t * d + p] : ((t == d) ? bq[p] : 0.f);
  __syncthreads();
  float s = -3.0e38f;
  if (t < d) {
    s = 0.f;
#pragma unroll 4
    for (int r = 0; r < D; r++) s += wq[r] * T[r * LDD + t];
  }
  red[t] = s; __syncthreads();
  for (int o = 128; o > 0; o >>= 1) { if (t < o) red[t] = fmaxf(red[t], red[t + o]); __syncthreads(); }
  float mx = red[0]; __syncthreads();
  float e = (t < d) ? expf(s - mx) : 0.f;
  red[t] = e; __syncthreads();
  for (int o = 128; o > 0; o >>= 1) { if (t < o) red[t] += red[t + o]; __syncthreads(); }
  float inv = 1.f / red[0];
  if (t < d) Pt[t * LDD + p] = e * inv;
}

// W' row j = Wv-hat[j,:] @ P^T
__global__ void k3d_all(P3 pv) {
  const int dTab[3] = {140, 112, 160};
  int br = blockIdx.x / 161;
  int j  = blockIdx.x - br * 161;
  int d = dTab[br];
  if (j > d) return;
  const float *Wv, *bv; sel(pv, br, Wv, bv);
  const float* Pt = g_Pt + br * GSTRIDE;
  float* Wp = g_Wp + br * GSTRIDE;
  __shared__ float wv[192];
  int t = threadIdx.x;               // 192
  if (t < d) wv[t] = (j < d) ? Wv[j * d + t] : bv[t];
  __syncthreads();
  if (t < d) {
    float s = 0.f;
#pragma unroll 4
    for (int l = 0; l < d; l++) s += wv[l] * Pt[l * LDD + t];
    Wp[j * LDD + t] = s;
  }
}

// ================= GEMM2 via mma.sync bf16 2-way split + ldmatrix =================
// D[128x64] = Bhat[128x192] @ Wp[192x64]
// split: D = Ah*Bh + Ah*Bl + Al*Bh, fp32 accum; 3 passes x 12 k-chunks of 16
// A smem: 128 rows x [Ah(192)|Al(192)] stride 392 bf16 (784 B == 16 mod 128: ldmatrix conflict-free)
// B smem: 64 rows  x [Bh(192)|Bl(192)] stride 392 bf16

#define G2_SA 392
#define G2_BOFF (128 * G2_SA)                  // B block offset in bf16 elems
#define G2_SMEM ((G2_BOFF + 64 * G2_SA) * 2)   // 150528 bytes

__device__ __forceinline__ uint32_t smem_u32(const void* p) {
  uint32_t a;
  asm("{ .reg .u64 t; cvta.to.shared.u64 t, %1; cvt.u32.u64 %0, t; }" : "=r"(a) : "l"(p));
  return a;
}

__device__ __forceinline__ void ldsm4(uint32_t* r, uint32_t addr) {
  asm volatile("ldmatrix.sync.aligned.m8n8.x4.shared.b16 {%0,%1,%2,%3}, [%4];"
               : "=r"(r[0]), "=r"(r[1]), "=r"(r[2]), "=r"(r[3]) : "r"(addr));
}

__device__ __forceinline__ void hmma16816(float* c, const uint32_t* a, uint32_t b0, uint32_t b1) {
  asm volatile(
      "mma.sync.aligned.m16n8k16.row.col.f32.bf16.bf16.f32 "
      "{%0,%1,%2,%3}, {%4,%5,%6,%7}, {%8,%9}, {%0,%1,%2,%3};"
      : "+f"(c[0]), "+f"(c[1]), "+f"(c[2]), "+f"(c[3])
      : "r"(a[0]), "r"(a[1]), "r"(a[2]), "r"(a[3]), "r"(b0), "r"(b1));
}

template<int BR>
__global__ void __launch_bounds__(256, 1) gemm2_hmma(float* __restrict__ out) {
  constexpr int d  = Tr<BR>::d;
  constexpr int w0 = Tr<BR>::w0, w1 = Tr<BR>::w1, w2 = Tr<BR>::w2;
  constexpr int s0 = Tr<BR>::s0, s1 = Tr<BR>::s1, s2 = Tr<BR>::s2;
  constexpr int pb0 = Tr<BR>::pb0, pb1 = Tr<BR>::pb1, pb2 = Tr<BR>::pb2;
  extern __shared__ __nv_bfloat16 smh[];
  __nv_bfloat16* Asm = smh;
  __nv_bfloat16* Bsm = smh + G2_BOFF;
  int t = threadIdx.x;
  int m0 = blockIdx.x * 128, n0 = blockIdx.y * 64;
  const float* Bg = g_B + (size_t)BR * AB_STRIDE;
  const float* Wp = g_Wp + BR * GSTRIDE;

  // ---- fill A planes: rows m0..m0+127, k 0..191, hi/lo split ----
  for (int i = t; i < 128 * 192; i += 256) {
    int row = i / 192, col = i - row * 192;
    float x = Bg[(size_t)(m0 + row) * LDD + col];
    __nv_bfloat16 h = __float2bfloat16(x);
    __nv_bfloat16 l = __float2bfloat16(x - __bfloat162float(h));
    Asm[row * G2_SA + col]       = h;
    Asm[row * G2_SA + 192 + col] = l;
  }
  // ---- fill B planes: Bmat[n][k] = Wp[k][n0+n] ----
  for (int i = t; i < 64 * 192; i += 256) {
    int n = i / 192, k = i - n * 192;
    float x = Wp[k * LDD + n0 + n];
    __nv_bfloat16 h = __float2bfloat16(x);
    __nv_bfloat16 l = __float2bfloat16(x - __bfloat162float(h));
    Bsm[n * G2_SA + k]       = h;
    Bsm[n * G2_SA + 192 + k] = l;
  }
  __syncthreads();

  // ---- warp tiling: 8 warps = 4(m) x 2(n); warp tile 32(m) x 32(n) ----
  int wid = t >> 5, lane = t & 31;
  int wm = wid & 3, wn = wid >> 2;
  int g = lane >> 2, c4 = lane & 3;
  uint32_t sbase = smem_u32(smh);
  int la = lane & 7;
  // A ldmatrix lane address: tiles {rows, rows+8} x {k, k+8}; lanes 0-7,8-15,16-23,24-31
  int aRow = wm * 32 + la + ((lane >> 3) & 1) * 8;
  int aCol = ((lane >> 4) & 1) * 8;
  uint32_t aBase = sbase + 2u * (uint32_t)(aRow * G2_SA + aCol);
  // B ldmatrix lane address: tiles {n-rows: b0}, {k+8: b1}, {n-rows+8}, {n+8,k+8}
  int bRow = wn * 32 + la + ((lane >> 4) & 1) * 8;
  int bCol = ((lane >> 3) & 1) * 8;
  uint32_t bBase = sbase + 2u * (uint32_t)(G2_BOFF + bRow * G2_SA + bCol);

  float acc[2][4][4] = {};
  for (int ps = 0; ps < 3; ps++) {
    int apl = (ps == 2) ? 192 : 0;
    int bpl = (ps == 1) ? 192 : 0;
#pragma unroll
    for (int kc = 0; kc < 12; kc++) {
      uint32_t a[2][4], bf[2][4];
#pragma unroll
      for (int mt = 0; mt < 2; mt++)
        ldsm4(a[mt], aBase + 2u * (uint32_t)(mt * 16 * G2_SA + apl + kc * 16));
#pragma unroll
      for (int np = 0; np < 2; np++)
        ldsm4(bf[np], bBase + 2u * (uint32_t)(np * 16 * G2_SA + bpl + kc * 16));
#pragma unroll
      for (int np = 0; np < 2; np++) {
        hmma16816(acc[0][np * 2],     a[0], bf[np][0], bf[np][1]);
        hmma16816(acc[1][np * 2],     a[1], bf[np][0], bf[np][1]);
        hmma16816(acc[0][np * 2 + 1], a[0], bf[np][2], bf[np][3]);
        hmma16816(acc[1][np * 2 + 1], a[1], bf[np][2], bf[np][3]);
      }
    }
  }

  // ---- scatter epilogue: fold + crop + branch transpose ----
#pragma unroll
  for (int mt = 0; mt < 2; mt++) {
#pragma unroll
    for (int hh = 0; hh < 2; hh++) {
      int m = m0 + wm * 32 + mt * 16 + g + hh * 8;
      int chn = m / 1000;
      int rem = m - chn * 1000;
      int ra  = (rem / 100) * w0 - pb0;
      int rb  = ((rem / 10) % 10) * w1 - pb1;
      int rcc = (rem % 10) * w2 - pb2;
#pragma unroll
      for (int nt = 0; nt < 4; nt++) {
#pragma unroll
        for (int e = 0; e < 2; e++) {
          int col = n0 + wn * 32 + nt * 8 + c4 * 2 + e;
          float val = acc[mt][nt][hh * 2 + e];
          if (col < d) {
            int x = col / (w1 * w2);
            int y = (col / w2) % w1;
            int z = col % w2;
            int u0 = ra + x, u1 = rb + y, u2 = rcc + z;
            if ((unsigned)u0 < (unsigned)s0 && (unsigned)u1 < (unsigned)s1 && (unsigned)u2 < (unsigned)s2) {
              long dst;
              if (BR == 0)      dst = ((long)(chn * 48 + u0) * 66 + u1) * 38 + u2;
              else if (BR == 1) dst = ((long)(chn * 38 + u0) * 66 + u2) * 38 + u1;
              else              dst = ((long)(chn * 48 + u2) * 78 + u1) * 38 + u0;
              out[Tr<BR>::OFF + dst] = val;
            }
          }
        }
      }
    }
  }
}

// ---------------- host driver ----------------
extern "C" void kernel_launch(void* const* d_in, const int* in_sizes, int n_in,
                              void* d_out, int out_size) {
  const float* axi   = (const float*)d_in[0];
  const float* cor   = (const float*)d_in[1];
  const float* sag   = (const float*)d_in[2];
  const float* atlas = (const float*)d_in[3];
  float* out = (float*)d_out;

  P3 pq = { (const float*)d_in[4],  (const float*)d_in[5],
            (const float*)d_in[10], (const float*)d_in[11],
            (const float*)d_in[16], (const float*)d_in[17] };
  P3 pk = { (const float*)d_in[6],  (const float*)d_in[7],
            (const float*)d_in[12], (const float*)d_in[13],
            (const float*)d_in[18], (const float*)d_in[19] };
  P3 pv = { (const float*)d_in[8],  (const float*)d_in[9],
            (const float*)d_in[14], (const float*)d_in[15],
            (const float*)d_in[20], (const float*)d_in[21] };

  cudaFuncSetAttribute(gemm2_hmma<0>, cudaFuncAttributeMaxDynamicSharedMemorySize, G2_SMEM);
  cudaFuncSetAttribute(gemm2_hmma<1>, cudaFuncAttributeMaxDynamicSharedMemorySize, G2_SMEM);
  cudaFuncSetAttribute(gemm2_hmma<2>, cudaFuncAttributeMaxDynamicSharedMemorySize, G2_SMEM);

  // split-M factors tuned for ~8 blocks/SM (148 SMs, 64-thread blocks)
  const int NS0 = 128, CH0 = (M_TOTAL + NS0 - 1) / NS0;
  const int NS1 = 288, CH1 = (M_TOTAL + NS1 - 1) / NS1;
  const int NS2 = 128, CH2 = (M_TOTAL + NS2 - 1) / NS2;

  zero_all<<<(3 * GSTRIDE + 255) / 256, 256>>>();
  packB_all<<<dim3(6400, 3), 256>>>(axi, cor, sag);

  packA_kernel<0><<<6400, 256>>>(atlas);
  gemm1_kernel<0><<<dim3(3, 3, NS0), 64>>>(CH0);
  packA_kernel<1><<<6400, 256>>>(atlas);
  gemm1_kernel<1><<<dim3(2, 2, NS1), 64>>>(CH1);
  packA_kernel<2><<<6400, 256>>>(atlas);
  gemm1_kernel<2><<<dim3(3, 3, NS2), 64>>>(CH2);

  k3a_all<<<3 * 161, 192>>>(pk);
  k3b_all<<<3 * 160, 256>>>(pq);
  k3d_all<<<3 * 161, 192>>>(pv);

  gemm2_hmma<0><<<dim3(500, 3), 256, G2_SMEM>>>(out);
  gemm2_hmma<1><<<dim3(500, 2), 256, G2_SMEM>>>(out);
  gemm2_hmma<2><<<dim3(500, 3), 256, G2_SMEM>>>(out);
}

// round 13
// speedup vs baseline: 1.3184x; 1.2830x over previous
#include <cuda_runtime.h>
#include <cstdint>

#define LDD 192
#define M_TOTAL 64000
#define AB_STRIDE ((size_t)M_TOTAL * LDD)
#define GSTRIDE (LDD * LDD)

// ---------------- scratch (static device globals; keep total well under ~256 MB) ----------------
static __device__ float g_B[3 * AB_STRIDE];   // ~147 MB (branch-batched)
static __device__ float g_A[AB_STRIDE];       // ~49 MB (shared, per-branch reuse)
static __device__ float g_G[3 * GSTRIDE];
static __device__ float g_T[3 * GSTRIDE];
static __device__ float g_Pt[3 * GSTRIDE];
static __device__ float g_Wp[3 * GSTRIDE];

// ---------------- per-branch compile-time traits ----------------
template<int BR> struct Tr;
template<> struct Tr<0> { // axi: s=(48,66,38) w=(5,7,4) d=140 pb=(1,2,1)
  static constexpr int w0=5,w1=7,w2=4,d=140,nt=3;
  static constexpr int s0=48,s1=66,s2=38;
  static constexpr int pb0=1,pb1=2,pb2=1;
  static constexpr long OFF=0;
};
template<> struct Tr<1> { // cor (internal transpose 0,1,2,4,3): s=(38,38,66) w=(4,4,7) d=112 pb=(1,1,2)
  static constexpr int w0=4,w1=4,w2=7,d=112,nt=2;
  static constexpr int s0=38,s1=38,s2=66;
  static constexpr int pb0=1,pb1=1,pb2=2;
  static constexpr long OFF=7704576;
};
template<> struct Tr<2> { // sag (internal transpose 0,1,4,3,2): s=(38,78,48) w=(4,8,5) d=160 pb=(1,1,1)
  static constexpr int w0=4,w1=8,w2=5,d=160,nt=3;
  static constexpr int s0=38,s1=78,s2=48;
  static constexpr int pb0=1,pb1=1,pb2=1;
  static constexpr long OFF=13804032;
};

template<int BR>
__device__ __forceinline__ void amap(int x, int y, int z, int& xb, int& yb, int& zb) {
  if (BR == 0) {
    xb = x; yb = (y * 6) / 7; zb = z;
  } else if (BR == 1) {
    int x2 = (x * 5) / 4, y2 = (y * 7) / 4, z2 = (z * 4) / 7;
    xb = x2; yb = (y2 * 6) / 7; zb = z2;
  } else {
    int y3 = y / 2, z3 = (z * 7) / 5;
    int x2 = (x * 5) / 4, y2 = (y3 * 7) / 4, z2 = (z3 * 4) / 7;
    xb = x2; yb = (y2 * 6) / 7; zb = z2;
  }
}

// ---------------- packB: gather B-hat for all branches in one launch ----------------
template<int BR>
__device__ void packB_body(const float* __restrict__ feat) {
  constexpr int w0=Tr<BR>::w0, w1=Tr<BR>::w1, w2=Tr<BR>::w2, d=Tr<BR>::d;
  constexpr int s0=Tr<BR>::s0, s1=Tr<BR>::s1, s2=Tr<BR>::s2;
  constexpr int pb0=Tr<BR>::pb0, pb1=Tr<BR>::pb1, pb2=Tr<BR>::pb2;
  float* Bdst = g_B + (size_t)BR * AB_STRIDE;
  int blk = blockIdx.x;
  int c = blk / 100;
  int a = (blk / 10) % 10;
  int b = blk % 10;
  for (int t = threadIdx.x; t < 10 * LDD; t += blockDim.x) {
    int cc = t / LDD;
    int j  = t - cc * LDD;
    int row = blk * 10 + cc;
    float vB;
    if (j < d) {
      int x = j / (w1 * w2);
      int y = (j / w2) % w1;
      int z = j % w2;
      int i0 = a * w0 + x - pb0;
      int i1 = b * w1 + y - pb1;
      int i2 = cc * w2 + z - pb2;
      vB = 0.f;
      if ((unsigned)i0 < (unsigned)s0 && (unsigned)i1 < (unsigned)s1 && (unsigned)i2 < (unsigned)s2) {
        int src;
        if (BR == 0)      src = ((c * 48 + i0) * 66 + i1) * 38 + i2;
        else if (BR == 1) src = ((c * 38 + i0) * 66 + i2) * 38 + i1;
        else              src = ((c * 48 + i2) * 78 + i1) * 38 + i0;
        vB = feat[src];
      }
    } else {
      vB = (j == d) ? 1.f : 0.f;
    }
    Bdst[(size_t)row * LDD + j] = vB;
  }
}

__global__ void packB_all(const float* __restrict__ axi, const float* __restrict__ cor,
                          const float* __restrict__ sag) {
  if (blockIdx.y == 0)      packB_body<0>(axi);
  else if (blockIdx.y == 1) packB_body<1>(cor);
  else                      packB_body<2>(sag);
}

// ---------------- packA: gather A-hat for one branch into shared buffer ----------------
template<int BR>
__global__ void packA_kernel(const float* __restrict__ atlas) {
  constexpr int w1=Tr<BR>::w1, w2=Tr<BR>::w2, d=Tr<BR>::d;
  int blk = blockIdx.x;
  int a = (blk / 10) % 10;
  int b = blk % 10;
  int c = blk / 100;
  for (int t = threadIdx.x; t < 10 * LDD; t += blockDim.x) {
    int cc = t / LDD;
    int j  = t - cc * LDD;
    int row = blk * 10 + cc;
    float vA;
    if (j < d) {
      int x = j / (w1 * w2);
      int y = (j / w2) % w1;
      int z = j % w2;
      int xb, yb, zb;
      amap<BR>(x, y, z, xb, yb, zb);
      int j0 = a * 5 + xb - 2;   // atlas aw=(5,6,4), pb=(2,2,1)
      int j1 = b * 6 + yb - 2;
      int j2 = cc * 4 + zb - 1;
      vA = 0.f;
      if ((unsigned)j0 < 46u && (unsigned)j1 < 56u && (unsigned)j2 < 38u)
        vA = atlas[((c * 46 + j0) * 56 + j1) * 38 + j2];
    } else {
      vA = (j == d) ? 1.f : 0.f;
    }
    g_A[(size_t)row * LDD + j] = vA;
  }
}

__global__ void zero_all() {
  int i = blockIdx.x * blockDim.x + threadIdx.x;
  if (i < 3 * GSTRIDE) { g_G[i] = 0.f; g_Wp[i] = 0.f; }
}

// ---------------- GEMM1: G = A-hat^T * B-hat, one branch, split-M, 8x8 micro ----------------
// chunk sizes are exact multiples of 16 and divide M_TOTAL exactly -> no bounds checks
template<int BR>
__global__ void __launch_bounds__(64, 8) gemm1_kernel(int mChunk) {
  int p0 = blockIdx.x * 64;
  int q0 = blockIdx.y * 64;
  int m0 = blockIdx.z * mChunk;
  int mHi = m0 + mChunk;
  const float* A  = g_A;
  const float* Bp = g_B + (size_t)BR * AB_STRIDE;
  float* G = g_G + BR * GSTRIDE;
  __shared__ alignas(16) float As[16][64];
  __shared__ alignas(16) float Bs[16][64];
  float acc[8][8] = {};
  int t = threadIdx.x;               // 64 threads
  int tx = t & 7, ty = t >> 3;
  int lr = t >> 4, lc = (t & 15) * 4;
  float4 pa[4], pb[4];
#define G1_LD(MB)                                                        \
  {                                                                      \
    _Pragma("unroll")                                                    \
    for (int i = 0; i < 4; i++) {                                        \
      int row = (MB) + lr + i * 4;                                       \
      pa[i] = *(const float4*)(A  + (size_t)row * LDD + p0 + lc);        \
      pb[i] = *(const float4*)(Bp + (size_t)row * LDD + q0 + lc);        \
    }                                                                    \
  }
  G1_LD(m0);
  for (int mb = m0; mb < mHi; mb += 16) {
    __syncthreads();
#pragma unroll
    for (int i = 0; i < 4; i++) {
      *(float4*)&As[lr + i * 4][lc] = pa[i];
      *(float4*)&Bs[lr + i * 4][lc] = pb[i];
    }
    __syncthreads();
    if (mb + 16 < mHi) G1_LD(mb + 16);
#pragma unroll
    for (int k = 0; k < 16; k++) {
      float a[8], b[8];
      *(float4*)&a[0] = *(float4*)&As[k][ty * 8];
      *(float4*)&a[4] = *(float4*)&As[k][ty * 8 + 4];
      *(float4*)&b[0] = *(float4*)&Bs[k][tx * 8];
      *(float4*)&b[4] = *(float4*)&Bs[k][tx * 8 + 4];
#pragma unroll
      for (int i = 0; i < 8; i++)
#pragma unroll
        for (int j = 0; j < 8; j++)
          acc[i][j] += a[i] * b[j];
    }
  }
#pragma unroll
  for (int i = 0; i < 8; i++)
#pragma unroll
    for (int j = 0; j < 8; j++)
      atomicAdd(&G[(p0 + ty * 8 + i) * LDD + q0 + tx * 8 + j], acc[i][j]);
#undef G1_LD
}

// ---------------- small chain (batched across branches) ----------------
struct P3 { const float* W0; const float* b0; const float* W1; const float* b1;
            const float* W2; const float* b2; };

__device__ __forceinline__ void sel(const P3& p, int br, const float*& W, const float*& b) {
  if (br == 0)      { W = p.W0; b = p.b0; }
  else if (br == 1) { W = p.W1; b = p.b1; }
  else              { W = p.W2; b = p.b2; }
}

// T = G-hat @ Wk-hat
__global__ void k3a_all(P3 pk) {
  const int dTab[3] = {140, 112, 160};
  int br = blockIdx.x / 161;
  int r  = blockIdx.x - br * 161;
  int d = dTab[br];
  if (r > d) return;
  const float *Wk, *bk; sel(pk, br, Wk, bk);
  const float* G = g_G + br * GSTRIDE;
  float* T = g_T + br * GSTRIDE;
  __shared__ float gsh[192];
  int t = threadIdx.x;               // 192
  gsh[t] = (t <= d) ? G[r * LDD + t] : 0.f;
  __syncthreads();
  if (t < d) {
    float s = gsh[d] * bk[t];
#pragma unroll 4
    for (int ss = 0; ss < d; ss++) s += gsh[ss] * Wk[ss * d + t];
    T[r * LDD + t] = s;
  }
}

// S row p = Wq-hat[:,p]^T @ T, fused softmax, write P transposed
__global__ void k3b_all(P3 pq) {
  const int dTab[3] = {140, 112, 160};
  int br = blockIdx.x / 160;
  int p  = blockIdx.x - br * 160;
  int d = dTab[br];
  if (p >= d) return;
  const float *Wq, *bq; sel(pq, br, Wq, bq);
  const float* T = g_T + br * GSTRIDE;
  float* Pt = g_Pt + br * GSTRIDE;
  __shared__ float wq[192];
  __shared__ float red[256];
  int t = threadIdx.x;               // 256
  int D = d + 1;
  if (t < 192) wq[t] = (t < d) ? Wq[t * d + p] : ((t == d) ? bq[p] : 0.f);
  __syncthreads();
  float s = -3.0e38f;
  if (t < d) {
    s = 0.f;
#pragma unroll 4
    for (int r = 0; r < D; r++) s += wq[r] * T[r * LDD + t];
  }
  red[t] = s; __syncthreads();
  for (int o = 128; o > 0; o >>= 1) { if (t < o) red[t] = fmaxf(red[t], red[t + o]); __syncthreads(); }
  float mx = red[0]; __syncthreads();
  float e = (t < d) ? expf(s - mx) : 0.f;
  red[t] = e; __syncthreads();
  for (int o = 128; o > 0; o >>= 1) { if (t < o) red[t] += red[t + o]; __syncthreads(); }
  float inv = 1.f / red[0];
  if (t < d) Pt[t * LDD + p] = e * inv;
}

// W' row j = Wv-hat[j,:] @ P^T
__global__ void k3d_all(P3 pv) {
  const int dTab[3] = {140, 112, 160};
  int br = blockIdx.x / 161;
  int j  = blockIdx.x - br * 161;
  int d = dTab[br];
  if (j > d) return;
  const float *Wv, *bv; sel(pv, br, Wv, bv);
  const float* Pt = g_Pt + br * GSTRIDE;
  float* Wp = g_Wp + br * GSTRIDE;
  __shared__ float wv[192];
  int t = threadIdx.x;               // 192
  if (t < d) wv[t] = (j < d) ? Wv[j * d + t] : bv[t];
  __syncthreads();
  if (t < d) {
    float s = 0.f;
#pragma unroll 4
    for (int l = 0; l < d; l++) s += wv[l] * Pt[l * LDD + t];
    Wp[j * LDD + t] = s;
  }
}

// ---------------- GEMM2: cross = B-hat @ W', 128x64 tile, 8x8 micro, fused scatter ----------------
template<int BR>
__device__ __forceinline__ void gemm2_body(float* __restrict__ out) {
  constexpr int d  = Tr<BR>::d;
  constexpr int w0 = Tr<BR>::w0, w1 = Tr<BR>::w1, w2 = Tr<BR>::w2;
  constexpr int s0 = Tr<BR>::s0, s1 = Tr<BR>::s1, s2 = Tr<BR>::s2;
  constexpr int pb0 = Tr<BR>::pb0, pb1 = Tr<BR>::pb1, pb2 = Tr<BR>::pb2;
  constexpr int KK = ((d + 1 + 15) / 16) * 16;
  int m0 = blockIdx.x * 128;
  int n0 = blockIdx.y * 64;
  const float* Bg = g_B + (size_t)BR * AB_STRIDE;
  const float* Wp = g_Wp + BR * GSTRIDE;
  __shared__ alignas(16) float Bs[16][128];    // transposed: Bs[k][m]
  __shared__ alignas(16) float Ws[16][64];
  float acc[8][8] = {};
  int t = threadIdx.x;               // 128 threads
  int tx = t & 7, ty = t >> 3;       // tx: n (0..7), ty: m (0..15)
  int lk = t >> 4, lc = (t & 15) * 4;
  float4 pbv[4], pwv[2];
#define G2_LD(K0)                                                          \
  {                                                                        \
    _Pragma("unroll")                                                      \
    for (int jj = 0; jj < 4; jj++)                                         \
      pbv[jj] = *(const float4*)(Bg + (size_t)(m0 + t) * LDD + (K0) + jj * 4); \
    pwv[0] = *(const float4*)(Wp + (size_t)((K0) + lk)     * LDD + n0 + lc);   \
    pwv[1] = *(const float4*)(Wp + (size_t)((K0) + lk + 8) * LDD + n0 + lc);   \
  }
  G2_LD(0);
  for (int k0 = 0; k0 < KK; k0 += 16) {
    __syncthreads();
#pragma unroll
    for (int jj = 0; jj < 4; jj++) {
      Bs[jj * 4 + 0][t] = pbv[jj].x;
      Bs[jj * 4 + 1][t] = pbv[jj].y;
      Bs[jj * 4 + 2][t] = pbv[jj].z;
      Bs[jj * 4 + 3][t] = pbv[jj].w;
    }
    *(float4*)&Ws[lk][lc]     = pwv[0];
    *(float4*)&Ws[lk + 8][lc] = pwv[1];
    __syncthreads();
    if (k0 + 16 < KK) G2_LD(k0 + 16);
#pragma unroll
    for (int k = 0; k < 16; k++) {
      float a[8], b[8];
      *(float4*)&a[0] = *(float4*)&Bs[k][ty * 8];
      *(float4*)&a[4] = *(float4*)&Bs[k][ty * 8 + 4];
      *(float4*)&b[0] = *(float4*)&Ws[k][tx * 8];
      *(float4*)&b[4] = *(float4*)&Ws[k][tx * 8 + 4];
#pragma unroll
      for (int i = 0; i < 8; i++)
#pragma unroll
        for (int j = 0; j < 8; j++)
          acc[i][j] += a[i] * b[j];
    }
  }
#undef G2_LD
  // epilogue: fold + crop + branch transpose, direct to output
  int rc[8], ra[8], rb[8], rcc[8];
#pragma unroll
  for (int i = 0; i < 8; i++) {
    int m = m0 + ty * 8 + i;
    int c = m / 1000;
    int rem = m - c * 1000;
    rc[i]  = c;
    ra[i]  = (rem / 100) * w0 - pb0;
    rb[i]  = ((rem / 10) % 10) * w1 - pb1;
    rcc[i] = (rem % 10) * w2 - pb2;
  }
  int cx[8], cy[8], cz[8]; bool cok[8];
#pragma unroll
  for (int j = 0; j < 8; j++) {
    int col = n0 + tx * 8 + j;
    cok[j] = col < d;
    cx[j] = col / (w1 * w2);
    cy[j] = (col / w2) % w1;
    cz[j] = col % w2;
  }
#pragma unroll
  for (int i = 0; i < 8; i++) {
#pragma unroll
    for (int j = 0; j < 8; j++) {
      if (cok[j]) {
        int u0 = ra[i] + cx[j];
        int u1 = rb[i] + cy[j];
        int u2 = rcc[i] + cz[j];
        if ((unsigned)u0 < (unsigned)s0 && (unsigned)u1 < (unsigned)s1 && (unsigned)u2 < (unsigned)s2) {
          long dst;
          if (BR == 0)      dst = ((long)(rc[i] * 48 + u0) * 66 + u1) * 38 + u2;
          else if (BR == 1) dst = ((long)(rc[i] * 38 + u0) * 66 + u2) * 38 + u1;
          else              dst = ((long)(rc[i] * 48 + u2) * 78 + u1) * 38 + u0;
          out[Tr<BR>::OFF + dst] = acc[i][j];
        }
      }
    }
  }
}

// single fused launch over (m-tiles, n-tiles, branch)
__global__ void __launch_bounds__(128, 4) gemm2_all(float* __restrict__ out) {
  if (blockIdx.z == 0)      { gemm2_body<0>(out); }
  else if (blockIdx.z == 1) { if (blockIdx.y < 2) gemm2_body<1>(out); }
  else                      { gemm2_body<2>(out); }
}

// ---------------- host driver ----------------
extern "C" void kernel_launch(void* const* d_in, const int* in_sizes, int n_in,
                              void* d_out, int out_size) {
  const float* axi   = (const float*)d_in[0];
  const float* cor   = (const float*)d_in[1];
  const float* sag   = (const float*)d_in[2];
  const float* atlas = (const float*)d_in[3];
  float* out = (float*)d_out;

  P3 pq = { (const float*)d_in[4],  (const float*)d_in[5],
            (const float*)d_in[10], (const float*)d_in[11],
            (const float*)d_in[16], (const float*)d_in[17] };
  P3 pk = { (const float*)d_in[6],  (const float*)d_in[7],
            (const float*)d_in[12], (const float*)d_in[13],
            (const float*)d_in[18], (const float*)d_in[19] };
  P3 pv = { (const float*)d_in[8],  (const float*)d_in[9],
            (const float*)d_in[14], (const float*)d_in[15],
            (const float*)d_in[20], (const float*)d_in[21] };

  // exact split-M: 64000 = 125*512 = 250*256 (no tail, unguarded loads)
  const int NS0 = 125, CH0 = 512;
  const int NS1 = 250, CH1 = 256;
  const int NS2 = 125, CH2 = 512;

  zero_all<<<(3 * GSTRIDE + 255) / 256, 256>>>();
  packB_all<<<dim3(6400, 3), 256>>>(axi, cor, sag);

  packA_kernel<0><<<6400, 256>>>(atlas);
  gemm1_kernel<0><<<dim3(3, 3, NS0), 64>>>(CH0);
  packA_kernel<1><<<6400, 256>>>(atlas);
  gemm1_kernel<1><<<dim3(2, 2, NS1), 64>>>(CH1);
  packA_kernel<2><<<6400, 256>>>(atlas);
  gemm1_kernel<2><<<dim3(3, 3, NS2), 64>>>(CH2);

  k3a_all<<<3 * 161, 192>>>(pk);
  k3b_all<<<3 * 160, 256>>>(pq);
  k3d_all<<<3 * 161, 192>>>(pv);

  gemm2_all<<<dim3(500, 3, 3), 128>>>(out);
}

// round 14
// speedup vs baseline: 1.3313x; 1.0098x over previous
#include <cuda_runtime.h>
#include <cstdint>

#define LDD 192
#define M_TOTAL 64000
#define AB_STRIDE ((size_t)M_TOTAL * LDD)
#define GSTRIDE (LDD * LDD)

// ---------------- scratch (static device globals; keep total well under ~256 MB) ----------------
static __device__ float g_B[3 * AB_STRIDE];   // ~147 MB (branch-batched)
static __device__ float g_A[AB_STRIDE];       // ~49 MB (shared, per-branch reuse)
static __device__ float g_G[3 * GSTRIDE];
static __device__ float g_T[3 * GSTRIDE];
static __device__ float g_Pt[3 * GSTRIDE];
static __device__ float g_Wp[3 * GSTRIDE];

// ---------------- per-branch compile-time traits ----------------
template<int BR> struct Tr;
template<> struct Tr<0> { // axi: s=(48,66,38) w=(5,7,4) d=140 pb=(1,2,1)
  static constexpr int w0=5,w1=7,w2=4,d=140,nt=3;
  static constexpr int s0=48,s1=66,s2=38;
  static constexpr int pb0=1,pb1=2,pb2=1;
  static constexpr long OFF=0;
};
template<> struct Tr<1> { // cor (internal transpose 0,1,2,4,3): s=(38,38,66) w=(4,4,7) d=112 pb=(1,1,2)
  static constexpr int w0=4,w1=4,w2=7,d=112,nt=2;
  static constexpr int s0=38,s1=38,s2=66;
  static constexpr int pb0=1,pb1=1,pb2=2;
  static constexpr long OFF=7704576;
};
template<> struct Tr<2> { // sag (internal transpose 0,1,4,3,2): s=(38,78,48) w=(4,8,5) d=160 pb=(1,1,1)
  static constexpr int w0=4,w1=8,w2=5,d=160,nt=3;
  static constexpr int s0=38,s1=78,s2=48;
  static constexpr int pb0=1,pb1=1,pb2=1;
  static constexpr long OFF=13804032;
};

template<int BR>
__device__ __forceinline__ void amap(int x, int y, int z, int& xb, int& yb, int& zb) {
  if (BR == 0) {
    xb = x; yb = (y * 6) / 7; zb = z;
  } else if (BR == 1) {
    int x2 = (x * 5) / 4, y2 = (y * 7) / 4, z2 = (z * 4) / 7;
    xb = x2; yb = (y2 * 6) / 7; zb = z2;
  } else {
    int y3 = y / 2, z3 = (z * 7) / 5;
    int x2 = (x * 5) / 4, y2 = (y3 * 7) / 4, z2 = (z3 * 4) / 7;
    xb = x2; yb = (y2 * 6) / 7; zb = z2;
  }
}

// ---------------- packB: gather B-hat for all branches in one launch ----------------
template<int BR>
__device__ void packB_body(const float* __restrict__ feat) {
  constexpr int w0=Tr<BR>::w0, w1=Tr<BR>::w1, w2=Tr<BR>::w2, d=Tr<BR>::d;
  constexpr int s0=Tr<BR>::s0, s1=Tr<BR>::s1, s2=Tr<BR>::s2;
  constexpr int pb0=Tr<BR>::pb0, pb1=Tr<BR>::pb1, pb2=Tr<BR>::pb2;
  float* Bdst = g_B + (size_t)BR * AB_STRIDE;
  int blk = blockIdx.x;
  int c = blk / 100;
  int a = (blk / 10) % 10;
  int b = blk % 10;
  for (int t = threadIdx.x; t < 10 * LDD; t += blockDim.x) {
    int cc = t / LDD;
    int j  = t - cc * LDD;
    int row = blk * 10 + cc;
    float vB;
    if (j < d) {
      int x = j / (w1 * w2);
      int y = (j / w2) % w1;
      int z = j % w2;
      int i0 = a * w0 + x - pb0;
      int i1 = b * w1 + y - pb1;
      int i2 = cc * w2 + z - pb2;
      vB = 0.f;
      if ((unsigned)i0 < (unsigned)s0 && (unsigned)i1 < (unsigned)s1 && (unsigned)i2 < (unsigned)s2) {
        int src;
        if (BR == 0)      src = ((c * 48 + i0) * 66 + i1) * 38 + i2;
        else if (BR == 1) src = ((c * 38 + i0) * 66 + i2) * 38 + i1;
        else              src = ((c * 48 + i2) * 78 + i1) * 38 + i0;
        vB = feat[src];
      }
    } else {
      vB = (j == d) ? 1.f : 0.f;
    }
    Bdst[(size_t)row * LDD + j] = vB;
  }
}

__global__ void packB_all(const float* __restrict__ axi, const float* __restrict__ cor,
                          const float* __restrict__ sag) {
  if (blockIdx.y == 0)      packB_body<0>(axi);
  else if (blockIdx.y == 1) packB_body<1>(cor);
  else                      packB_body<2>(sag);
}

// ---------------- packA: gather A-hat for one branch into shared buffer ----------------
template<int BR>
__global__ void packA_kernel(const float* __restrict__ atlas) {
  constexpr int w1=Tr<BR>::w1, w2=Tr<BR>::w2, d=Tr<BR>::d;
  int blk = blockIdx.x;
  int a = (blk / 10) % 10;
  int b = blk % 10;
  int c = blk / 100;
  for (int t = threadIdx.x; t < 10 * LDD; t += blockDim.x) {
    int cc = t / LDD;
    int j  = t - cc * LDD;
    int row = blk * 10 + cc;
    float vA;
    if (j < d) {
      int x = j / (w1 * w2);
      int y = (j / w2) % w1;
      int z = j % w2;
      int xb, yb, zb;
      amap<BR>(x, y, z, xb, yb, zb);
      int j0 = a * 5 + xb - 2;   // atlas aw=(5,6,4), pb=(2,2,1)
      int j1 = b * 6 + yb - 2;
      int j2 = cc * 4 + zb - 1;
      vA = 0.f;
      if ((unsigned)j0 < 46u && (unsigned)j1 < 56u && (unsigned)j2 < 38u)
        vA = atlas[((c * 46 + j0) * 56 + j1) * 38 + j2];
    } else {
      vA = (j == d) ? 1.f : 0.f;
    }
    g_A[(size_t)row * LDD + j] = vA;
  }
}

__global__ void zero_all() {
  int i = blockIdx.x * blockDim.x + threadIdx.x;
  if (i < 3 * GSTRIDE) { g_G[i] = 0.f; g_Wp[i] = 0.f; }
}

// ---------------- GEMM1: G = A-hat^T * B-hat, tile TT x TT (TT=48/64/56), 64 threads ----------------
// exact chunking (no bounds checks); micro = TT/8 per thread
template<int BR, int TT>
__global__ void __launch_bounds__(64, 8) gemm1_kernel(int mChunk) {
  constexpr int MI = TT / 8;          // microtile per thread
  constexpr int F2 = TT / 8;          // float2 loads per thread per row-group
  int p0 = blockIdx.x * TT;
  int q0 = blockIdx.y * TT;
  int m0 = blockIdx.z * mChunk;
  int mHi = m0 + mChunk;
  const float* A  = g_A;
  const float* Bp = g_B + (size_t)BR * AB_STRIDE;
  float* G = g_G + BR * GSTRIDE;
  __shared__ alignas(16) float As[16][TT];
  __shared__ alignas(16) float Bs[16][TT];
  float acc[MI][MI] = {};
  int t = threadIdx.x;               // 64 threads
  int tx = t & 7, ty = t >> 3;
  int lr = t >> 2;                   // row 0..15
  int lp = t & 3;                    // 4 threads per row
  float2 pa[F2], pb[F2];
#define G1_LD(MB)                                                          \
  {                                                                        \
    const float* ar = A  + (size_t)((MB) + lr) * LDD + p0;                 \
    const float* br = Bp + (size_t)((MB) + lr) * LDD + q0;                 \
    _Pragma("unroll")                                                      \
    for (int i = 0; i < F2; i++) {                                         \
      pa[i] = *(const float2*)(ar + (lp * F2 + i) * 2);                    \
      pb[i] = *(const float2*)(br + (lp * F2 + i) * 2);                    \
    }                                                                      \
  }
  G1_LD(m0);
  for (int mb = m0; mb < mHi; mb += 16) {
    __syncthreads();
#pragma unroll
    for (int i = 0; i < F2; i++) {
      *(float2*)&As[lr][(lp * F2 + i) * 2] = pa[i];
      *(float2*)&Bs[lr][(lp * F2 + i) * 2] = pb[i];
    }
    __syncthreads();
    if (mb + 16 < mHi) G1_LD(mb + 16);
#pragma unroll
    for (int k = 0; k < 16; k++) {
      float a[MI], b[MI];
#pragma unroll
      for (int i = 0; i < MI; i++) a[i] = As[k][ty * MI + i];
#pragma unroll
      for (int j = 0; j < MI; j++) b[j] = Bs[k][tx * MI + j];
#pragma unroll
      for (int i = 0; i < MI; i++)
#pragma unroll
        for (int j = 0; j < MI; j++)
          acc[i][j] += a[i] * b[j];
    }
  }
#pragma unroll
  for (int i = 0; i < MI; i++)
#pragma unroll
    for (int j = 0; j < MI; j++)
      atomicAdd(&G[(p0 + ty * MI + i) * LDD + q0 + tx * MI + j], acc[i][j]);
#undef G1_LD
}

// ---------------- small chain (batched across branches) ----------------
struct P3 { const float* W0; const float* b0; const float* W1; const float* b1;
            const float* W2; const float* b2; };

__device__ __forceinline__ void sel(const P3& p, int br, const float*& W, const float*& b) {
  if (br == 0)      { W = p.W0; b = p.b0; }
  else if (br == 1) { W = p.W1; b = p.b1; }
  else              { W = p.W2; b = p.b2; }
}

// T = G-hat @ Wk-hat
__global__ void k3a_all(P3 pk) {
  const int dTab[3] = {140, 112, 160};
  int br = blockIdx.x / 161;
  int r  = blockIdx.x - br * 161;
  int d = dTab[br];
  if (r > d) return;
  const float *Wk, *bk; sel(pk, br, Wk, bk);
  const float* G = g_G + br * GSTRIDE;
  float* T = g_T + br * GSTRIDE;
  __shared__ float gsh[192];
  int t = threadIdx.x;               // 192
  gsh[t] = (t <= d) ? G[r * LDD + t] : 0.f;
  __syncthreads();
  if (t < d) {
    float s = gsh[d] * bk[t];
#pragma unroll 4
    for (int ss = 0; ss < d; ss++) s += gsh[ss] * Wk[ss * d + t];
    T[r * LDD + t] = s;
  }
}

// S row p = Wq-hat[:,p]^T @ T, fused softmax, write P transposed
__global__ void k3b_all(P3 pq) {
  const int dTab[3] = {140, 112, 160};
  int br = blockIdx.x / 160;
  int p  = blockIdx.x - br * 160;
  int d = dTab[br];
  if (p >= d) return;
  const float *Wq, *bq; sel(pq, br, Wq, bq);
  const float* T = g_T + br * GSTRIDE;
  float* Pt = g_Pt + br * GSTRIDE;
  __shared__ float wq[192];
  __shared__ float red[256];
  int t = threadIdx.x;               // 256
  int D = d + 1;
  if (t < 192) wq[t] = (t < d) ? Wq[t * d + p] : ((t == d) ? bq[p] : 0.f);
  __syncthreads();
  float s = -3.0e38f;
  if (t < d) {
    s = 0.f;
#pragma unroll 4
    for (int r = 0; r < D; r++) s += wq[r] * T[r * LDD + t];
  }
  red[t] = s; __syncthreads();
  for (int o = 128; o > 0; o >>= 1) { if (t < o) red[t] = fmaxf(red[t], red[t + o]); __syncthreads(); }
  float mx = red[0]; __syncthreads();
  float e = (t < d) ? expf(s - mx) : 0.f;
  red[t] = e; __syncthreads();
  for (int o = 128; o > 0; o >>= 1) { if (t < o) red[t] += red[t + o]; __syncthreads(); }
  float inv = 1.f / red[0];
  if (t < d) Pt[t * LDD + p] = e * inv;
}

// W' row j = Wv-hat[j,:] @ P^T
__global__ void k3d_all(P3 pv) {
  const int dTab[3] = {140, 112, 160};
  int br = blockIdx.x / 161;
  int j  = blockIdx.x - br * 161;
  int d = dTab[br];
  if (j > d) return;
  const float *Wv, *bv; sel(pv, br, Wv, bv);
  const float* Pt = g_Pt + br * GSTRIDE;
  float* Wp = g_Wp + br * GSTRIDE;
  __shared__ float wv[192];
  int t = threadIdx.x;               // 192
  if (t < d) wv[t] = (j < d) ? Wv[j * d + t] : bv[t];
  __syncthreads();
  if (t < d) {
    float s = 0.f;
#pragma unroll 4
    for (int l = 0; l < d; l++) s += wv[l] * Pt[l * LDD + t];
    Wp[j * LDD + t] = s;
  }
}

// ---------------- GEMM2: cross = B-hat @ W', 128x64 tile, 8x8 micro, fused scatter ----------------
template<int BR>
__device__ __forceinline__ void gemm2_body(float* __restrict__ out) {
  constexpr int d  = Tr<BR>::d;
  constexpr int w0 = Tr<BR>::w0, w1 = Tr<BR>::w1, w2 = Tr<BR>::w2;
  constexpr int s0 = Tr<BR>::s0, s1 = Tr<BR>::s1, s2 = Tr<BR>::s2;
  constexpr int pb0 = Tr<BR>::pb0, pb1 = Tr<BR>::pb1, pb2 = Tr<BR>::pb2;
  constexpr int KK = ((d + 1 + 15) / 16) * 16;
  int m0 = blockIdx.x * 128;
  int n0 = blockIdx.y * 64;
  const float* Bg = g_B + (size_t)BR * AB_STRIDE;
  const float* Wp = g_Wp + BR * GSTRIDE;
  __shared__ alignas(16) float Bs[16][128];    // transposed: Bs[k][m]
  __shared__ alignas(16) float Ws[16][64];
  float acc[8][8] = {};
  int t = threadIdx.x;               // 128 threads
  int tx = t & 7, ty = t >> 3;       // tx: n (0..7), ty: m (0..15)
  int lk = t >> 4, lc = (t & 15) * 4;
  float4 pbv[4], pwv[2];
#define G2_LD(K0)                                                          \
  {                                                                        \
    _Pragma("unroll")                                                      \
    for (int jj = 0; jj < 4; jj++)                                         \
      pbv[jj] = *(const float4*)(Bg + (size_t)(m0 + t) * LDD + (K0) + jj * 4); \
    pwv[0] = *(const float4*)(Wp + (size_t)((K0) + lk)     * LDD + n0 + lc);   \
    pwv[1] = *(const float4*)(Wp + (size_t)((K0) + lk + 8) * LDD + n0 + lc);   \
  }
  G2_LD(0);
  for (int k0 = 0; k0 < KK; k0 += 16) {
    __syncthreads();
#pragma unroll
    for (int jj = 0; jj < 4; jj++) {
      Bs[jj * 4 + 0][t] = pbv[jj].x;
      Bs[jj * 4 + 1][t] = pbv[jj].y;
      Bs[jj * 4 + 2][t] = pbv[jj].z;
      Bs[jj * 4 + 3][t] = pbv[jj].w;
    }
    *(float4*)&Ws[lk][lc]     = pwv[0];
    *(float4*)&Ws[lk + 8][lc] = pwv[1];
    __syncthreads();
    if (k0 + 16 < KK) G2_LD(k0 + 16);
#pragma unroll
    for (int k = 0; k < 16; k++) {
      float a[8], b[8];
      *(float4*)&a[0] = *(float4*)&Bs[k][ty * 8];
      *(float4*)&a[4] = *(float4*)&Bs[k][ty * 8 + 4];
      *(float4*)&b[0] = *(float4*)&Ws[k][tx * 8];
      *(float4*)&b[4] = *(float4*)&Ws[k][tx * 8 + 4];
#pragma unroll
      for (int i = 0; i < 8; i++)
#pragma unroll
        for (int j = 0; j < 8; j++)
          acc[i][j] += a[i] * b[j];
    }
  }
#undef G2_LD
  // epilogue: fold + crop + branch transpose, direct to output
  int rc[8], ra[8], rb[8], rcc[8];
#pragma unroll
  for (int i = 0; i < 8; i++) {
    int m = m0 + ty * 8 + i;
    int c = m / 1000;
    int rem = m - c * 1000;
    rc[i]  = c;
    ra[i]  = (rem / 100) * w0 - pb0;
    rb[i]  = ((rem / 10) % 10) * w1 - pb1;
    rcc[i] = (rem % 10) * w2 - pb2;
  }
  int cx[8], cy[8], cz[8]; bool cok[8];
#pragma unroll
  for (int j = 0; j < 8; j++) {
    int col = n0 + tx * 8 + j;
    cok[j] = col < d;
    cx[j] = col / (w1 * w2);
    cy[j] = (col / w2) % w1;
    cz[j] = col % w2;
  }
#pragma unroll
  for (int i = 0; i < 8; i++) {
#pragma unroll
    for (int j = 0; j < 8; j++) {
      if (cok[j]) {
        int u0 = ra[i] + cx[j];
        int u1 = rb[i] + cy[j];
        int u2 = rcc[i] + cz[j];
        if ((unsigned)u0 < (unsigned)s0 && (unsigned)u1 < (unsigned)s1 && (unsigned)u2 < (unsigned)s2) {
          long dst;
          if (BR == 0)      dst = ((long)(rc[i] * 48 + u0) * 66 + u1) * 38 + u2;
          else if (BR == 1) dst = ((long)(rc[i] * 38 + u0) * 66 + u2) * 38 + u1;
          else              dst = ((long)(rc[i] * 48 + u2) * 78 + u1) * 38 + u0;
          out[Tr<BR>::OFF + dst] = acc[i][j];
        }
      }
    }
  }
}

// single fused launch over (m-tiles, n-tiles, branch)
__global__ void __launch_bounds__(128, 4) gemm2_all(float* __restrict__ out) {
  if (blockIdx.z == 0)      { gemm2_body<0>(out); }
  else if (blockIdx.z == 1) { if (blockIdx.y < 2) gemm2_body<1>(out); }
  else                      { gemm2_body<2>(out); }
}

// ---------------- host driver ----------------
extern "C" void kernel_launch(void* const* d_in, const int* in_sizes, int n_in,
                              void* d_out, int out_size) {
  const float* axi   = (const float*)d_in[0];
  const float* cor   = (const float*)d_in[1];
  const float* sag   = (const float*)d_in[2];
  const float* atlas = (const float*)d_in[3];
  float* out = (float*)d_out;

  P3 pq = { (const float*)d_in[4],  (const float*)d_in[5],
            (const float*)d_in[10], (const float*)d_in[11],
            (const float*)d_in[16], (const float*)d_in[17] };
  P3 pk = { (const float*)d_in[6],  (const float*)d_in[7],
            (const float*)d_in[12], (const float*)d_in[13],
            (const float*)d_in[18], (const float*)d_in[19] };
  P3 pv = { (const float*)d_in[8],  (const float*)d_in[9],
            (const float*)d_in[14], (const float*)d_in[15],
            (const float*)d_in[20], (const float*)d_in[21] };

  // exact split-M: 64000 = 125*512 = 250*256 (no tail, unguarded loads)
  const int NS0 = 125, CH0 = 512;
  const int NS1 = 250, CH1 = 256;
  const int NS2 = 125, CH2 = 512;

  zero_all<<<(3 * GSTRIDE + 255) / 256, 256>>>();
  packB_all<<<dim3(6400, 3), 256>>>(axi, cor, sag);

  // tile widths: br0 48 (3x3 covers 144>=141), br1 64 (2x2 covers 128>=113), br2 56 (3x3 covers 168>=161)
  packA_kernel<0><<<6400, 256>>>(atlas);
  gemm1_kernel<0, 48><<<dim3(3, 3, NS0), 64>>>(CH0);
  packA_kernel<1><<<6400, 256>>>(atlas);
  gemm1_kernel<1, 64><<<dim3(2, 2, NS1), 64>>>(CH1);
  packA_kernel<2><<<6400, 256>>>(atlas);
  gemm1_kernel<2, 56><<<dim3(3, 3, NS2), 64>>>(CH2);

  k3a_all<<<3 * 161, 192>>>(pk);
  k3b_all<<<3 * 160, 256>>>(pq);
  k3d_all<<<3 * 161, 192>>>(pv);

  gemm2_all<<<dim3(500, 3, 3), 128>>>(out);
}

// round 15
// speedup vs baseline: 1.4769x; 1.1094x over previous
#include <cuda_runtime.h>
#include <cstdint>

#define LDD 192
#define M_TOTAL 64000
#define AB_STRIDE ((size_t)M_TOTAL * LDD)
#define GSTRIDE (LDD * LDD)

// ---------------- scratch (static device globals; keep total well under ~256 MB) ----------------
static __device__ float g_B[3 * AB_STRIDE];   // ~147 MB (branch-batched)
static __device__ float g_A[AB_STRIDE];       // ~49 MB (shared, per-branch reuse)
static __device__ float g_G[3 * GSTRIDE];
static __device__ float g_T[3 * GSTRIDE];
static __device__ float g_Pt[3 * GSTRIDE];
static __device__ float g_Wp[3 * GSTRIDE];

// ---------------- per-branch compile-time traits ----------------
template<int BR> struct Tr;
template<> struct Tr<0> { // axi: s=(48,66,38) w=(5,7,4) d=140 pb=(1,2,1)
  static constexpr int w0=5,w1=7,w2=4,d=140,nt=3;
  static constexpr int s0=48,s1=66,s2=38;
  static constexpr int pb0=1,pb1=2,pb2=1;
  static constexpr long OFF=0;
};
template<> struct Tr<1> { // cor (internal transpose 0,1,2,4,3): s=(38,38,66) w=(4,4,7) d=112 pb=(1,1,2)
  static constexpr int w0=4,w1=4,w2=7,d=112,nt=2;
  static constexpr int s0=38,s1=38,s2=66;
  static constexpr int pb0=1,pb1=1,pb2=2;
  static constexpr long OFF=7704576;
};
template<> struct Tr<2> { // sag (internal transpose 0,1,4,3,2): s=(38,78,48) w=(4,8,5) d=160 pb=(1,1,1)
  static constexpr int w0=4,w1=8,w2=5,d=160,nt=3;
  static constexpr int s0=38,s1=78,s2=48;
  static constexpr int pb0=1,pb1=1,pb2=1;
  static constexpr long OFF=13804032;
};

template<int BR>
__device__ __forceinline__ void amap(int x, int y, int z, int& xb, int& yb, int& zb) {
  if (BR == 0) {
    xb = x; yb = (y * 6) / 7; zb = z;
  } else if (BR == 1) {
    int x2 = (x * 5) / 4, y2 = (y * 7) / 4, z2 = (z * 4) / 7;
    xb = x2; yb = (y2 * 6) / 7; zb = z2;
  } else {
    int y3 = y / 2, z3 = (z * 7) / 5;
    int x2 = (x * 5) / 4, y2 = (y3 * 7) / 4, z2 = (z3 * 4) / 7;
    xb = x2; yb = (y2 * 6) / 7; zb = z2;
  }
}

// ---------------- packB: gather B-hat for all branches in one launch ----------------
template<int BR>
__device__ void packB_body(const float* __restrict__ feat) {
  constexpr int w0=Tr<BR>::w0, w1=Tr<BR>::w1, w2=Tr<BR>::w2, d=Tr<BR>::d;
  constexpr int s0=Tr<BR>::s0, s1=Tr<BR>::s1, s2=Tr<BR>::s2;
  constexpr int pb0=Tr<BR>::pb0, pb1=Tr<BR>::pb1, pb2=Tr<BR>::pb2;
  float* Bdst = g_B + (size_t)BR * AB_STRIDE;
  int blk = blockIdx.x;
  int c = blk / 100;
  int a = (blk / 10) % 10;
  int b = blk % 10;
  for (int t = threadIdx.x; t < 10 * LDD; t += blockDim.x) {
    int cc = t / LDD;
    int j  = t - cc * LDD;
    int row = blk * 10 + cc;
    float vB;
    if (j < d) {
      int x = j / (w1 * w2);
      int y = (j / w2) % w1;
      int z = j % w2;
      int i0 = a * w0 + x - pb0;
      int i1 = b * w1 + y - pb1;
      int i2 = cc * w2 + z - pb2;
      vB = 0.f;
      if ((unsigned)i0 < (unsigned)s0 && (unsigned)i1 < (unsigned)s1 && (unsigned)i2 < (unsigned)s2) {
        int src;
        if (BR == 0)      src = ((c * 48 + i0) * 66 + i1) * 38 + i2;
        else if (BR == 1) src = ((c * 38 + i0) * 66 + i2) * 38 + i1;
        else              src = ((c * 48 + i2) * 78 + i1) * 38 + i0;
        vB = feat[src];
      }
    } else {
      vB = (j == d) ? 1.f : 0.f;
    }
    Bdst[(size_t)row * LDD + j] = vB;
  }
}

__global__ void packB_all(const float* __restrict__ axi, const float* __restrict__ cor,
                          const float* __restrict__ sag) {
  if (blockIdx.y == 0)      packB_body<0>(axi);
  else if (blockIdx.y == 1) packB_body<1>(cor);
  else                      packB_body<2>(sag);
}

// ---------------- packA: gather A-hat for one branch into shared buffer ----------------
template<int BR>
__global__ void packA_kernel(const float* __restrict__ atlas) {
  constexpr int w1=Tr<BR>::w1, w2=Tr<BR>::w2, d=Tr<BR>::d;
  int blk = blockIdx.x;
  int a = (blk / 10) % 10;
  int b = blk % 10;
  int c = blk / 100;
  for (int t = threadIdx.x; t < 10 * LDD; t += blockDim.x) {
    int cc = t / LDD;
    int j  = t - cc * LDD;
    int row = blk * 10 + cc;
    float vA;
    if (j < d) {
      int x = j / (w1 * w2);
      int y = (j / w2) % w1;
      int z = j % w2;
      int xb, yb, zb;
      amap<BR>(x, y, z, xb, yb, zb);
      int j0 = a * 5 + xb - 2;   // atlas aw=(5,6,4), pb=(2,2,1)
      int j1 = b * 6 + yb - 2;
      int j2 = cc * 4 + zb - 1;
      vA = 0.f;
      if ((unsigned)j0 < 46u && (unsigned)j1 < 56u && (unsigned)j2 < 38u)
        vA = atlas[((c * 46 + j0) * 56 + j1) * 38 + j2];
    } else {
      vA = (j == d) ? 1.f : 0.f;
    }
    g_A[(size_t)row * LDD + j] = vA;
  }
}

__global__ void zero_all() {
  int i = blockIdx.x * blockDim.x + threadIdx.x;
  if (i < 3 * GSTRIDE) { g_G[i] = 0.f; g_Wp[i] = 0.f; }
}

// ---------------- GEMM1: G = A-hat^T * B-hat, tile TT x TT (TT=48/64/56), 64 threads ----------------
template<int BR, int TT>
__global__ void __launch_bounds__(64, 8) gemm1_kernel(int mChunk) {
  constexpr int MI = TT / 8;
  constexpr int F2 = TT / 8;
  int p0 = blockIdx.x * TT;
  int q0 = blockIdx.y * TT;
  int m0 = blockIdx.z * mChunk;
  int mHi = m0 + mChunk;
  const float* A  = g_A;
  const float* Bp = g_B + (size_t)BR * AB_STRIDE;
  float* G = g_G + BR * GSTRIDE;
  __shared__ alignas(16) float As[16][TT];
  __shared__ alignas(16) float Bs[16][TT];
  float acc[MI][MI] = {};
  int t = threadIdx.x;               // 64 threads
  int tx = t & 7, ty = t >> 3;
  int lr = t >> 2;                   // row 0..15
  int lp = t & 3;                    // 4 threads per row
  float2 pa[F2], pb[F2];
#define G1_LD(MB)                                                          \
  {                                                                        \
    const float* ar = A  + (size_t)((MB) + lr) * LDD + p0;                 \
    const float* br = Bp + (size_t)((MB) + lr) * LDD + q0;                 \
    _Pragma("unroll")                                                      \
    for (int i = 0; i < F2; i++) {                                         \
      pa[i] = *(const float2*)(ar + (lp * F2 + i) * 2);                    \
      pb[i] = *(const float2*)(br + (lp * F2 + i) * 2);                    \
    }                                                                      \
  }
  G1_LD(m0);
  for (int mb = m0; mb < mHi; mb += 16) {
    __syncthreads();
#pragma unroll
    for (int i = 0; i < F2; i++) {
      *(float2*)&As[lr][(lp * F2 + i) * 2] = pa[i];
      *(float2*)&Bs[lr][(lp * F2 + i) * 2] = pb[i];
    }
    __syncthreads();
    if (mb + 16 < mHi) G1_LD(mb + 16);
#pragma unroll
    for (int k = 0; k < 16; k++) {
      float a[MI], b[MI];
      if (MI % 2 == 0) {   // ty*MI*4 bytes divisible by 8 -> float2 LDS
#pragma unroll
        for (int i = 0; i < MI / 2; i++) {
          float2 va = *(float2*)&As[k][ty * MI + 2 * i];
          float2 vb = *(float2*)&Bs[k][tx * MI + 2 * i];
          a[2 * i] = va.x; a[2 * i + 1] = va.y;
          b[2 * i] = vb.x; b[2 * i + 1] = vb.y;
        }
      } else {
#pragma unroll
        for (int i = 0; i < MI; i++) a[i] = As[k][ty * MI + i];
#pragma unroll
        for (int j = 0; j < MI; j++) b[j] = Bs[k][tx * MI + j];
      }
#pragma unroll
      for (int i = 0; i < MI; i++)
#pragma unroll
        for (int j = 0; j < MI; j++)
          acc[i][j] += a[i] * b[j];
    }
  }
#pragma unroll
  for (int i = 0; i < MI; i++)
#pragma unroll
    for (int j = 0; j < MI; j++)
      atomicAdd(&G[(p0 + ty * MI + i) * LDD + q0 + tx * MI + j], acc[i][j]);
#undef G1_LD
}

// ---------------- small chain (batched across branches) ----------------
struct P3 { const float* W0; const float* b0; const float* W1; const float* b1;
            const float* W2; const float* b2; };

__device__ __forceinline__ void sel(const P3& p, int br, const float*& W, const float*& b) {
  if (br == 0)      { W = p.W0; b = p.b0; }
  else if (br == 1) { W = p.W1; b = p.b1; }
  else              { W = p.W2; b = p.b2; }
}

// T = G-hat @ Wk-hat
__global__ void k3a_all(P3 pk) {
  const int dTab[3] = {140, 112, 160};
  int br = blockIdx.x / 161;
  int r  = blockIdx.x - br * 161;
  int d = dTab[br];
  if (r > d) return;
  const float *Wk, *bk; sel(pk, br, Wk, bk);
  const float* G = g_G + br * GSTRIDE;
  float* T = g_T + br * GSTRIDE;
  __shared__ float gsh[192];
  int t = threadIdx.x;               // 192
  gsh[t] = (t <= d) ? G[r * LDD + t] : 0.f;
  __syncthreads();
  if (t < d) {
    float s = gsh[d] * bk[t];
#pragma unroll 4
    for (int ss = 0; ss < d; ss++) s += gsh[ss] * Wk[ss * d + t];
    T[r * LDD + t] = s;
  }
}

// S row p = Wq-hat[:,p]^T @ T, fused softmax, write P transposed
__global__ void k3b_all(P3 pq) {
  const int dTab[3] = {140, 112, 160};
  int br = blockIdx.x / 160;
  int p  = blockIdx.x - br * 160;
  int d = dTab[br];
  if (p >= d) return;
  const float *Wq, *bq; sel(pq, br, Wq, bq);
  const float* T = g_T + br * GSTRIDE;
  float* Pt = g_Pt + br * GSTRIDE;
  __shared__ float wq[192];
  __shared__ float red[256];
  int t = threadIdx.x;               // 256
  int D = d + 1;
  if (t < 192) wq[t] = (t < d) ? Wq[t * d + p] : ((t == d) ? bq[p] : 0.f);
  __syncthreads();
  float s = -3.0e38f;
  if (t < d) {
    s = 0.f;
#pragma unroll 4
    for (int r = 0; r < D; r++) s += wq[r] * T[r * LDD + t];
  }
  red[t] = s; __syncthreads();
  for (int o = 128; o > 0; o >>= 1) { if (t < o) red[t] = fmaxf(red[t], red[t + o]); __syncthreads(); }
  float mx = red[0]; __syncthreads();
  float e = (t < d) ? expf(s - mx) : 0.f;
  red[t] = e; __syncthreads();
  for (int o = 128; o > 0; o >>= 1) { if (t < o) red[t] += red[t + o]; __syncthreads(); }
  float inv = 1.f / red[0];
  if (t < d) Pt[t * LDD + p] = e * inv;
}

// W' row j = Wv-hat[j,:] @ P^T
__global__ void k3d_all(P3 pv) {
  const int dTab[3] = {140, 112, 160};
  int br = blockIdx.x / 161;
  int j  = blockIdx.x - br * 161;
  int d = dTab[br];
  if (j > d) return;
  const float *Wv, *bv; sel(pv, br, Wv, bv);
  const float* Pt = g_Pt + br * GSTRIDE;
  float* Wp = g_Wp + br * GSTRIDE;
  __shared__ float wv[192];
  int t = threadIdx.x;               // 192
  if (t < d) wv[t] = (j < d) ? Wv[j * d + t] : bv[t];
  __syncthreads();
  if (t < d) {
    float s = 0.f;
#pragma unroll 4
    for (int l = 0; l < d; l++) s += wv[l] * Pt[l * LDD + t];
    Wp[j * LDD + t] = s;
  }
}

// ---------------- GEMM2: cross = B-hat @ W', 128 x TN tile (TN=48/56/56), fused scatter ----------------
template<int BR, int TN>
__device__ __forceinline__ void gemm2_body(float* __restrict__ out) {
  constexpr int d  = Tr<BR>::d;
  constexpr int w0 = Tr<BR>::w0, w1 = Tr<BR>::w1, w2 = Tr<BR>::w2;
  constexpr int s0 = Tr<BR>::s0, s1 = Tr<BR>::s1, s2 = Tr<BR>::s2;
  constexpr int pb0 = Tr<BR>::pb0, pb1 = Tr<BR>::pb1, pb2 = Tr<BR>::pb2;
  constexpr int KK = ((d + 1 + 15) / 16) * 16;
  constexpr int TNI = TN / 8;                 // n per thread (6 or 7)
  constexpr int WPT = (16 * TN) / 128;        // Ws floats per thread
  int m0 = blockIdx.x * 128;
  int n0 = blockIdx.y * TN;
  const float* Bg = g_B + (size_t)BR * AB_STRIDE;
  const float* Wp = g_Wp + BR * GSTRIDE;
  __shared__ alignas(16) float Bs[16][128];    // transposed: Bs[k][m]
  __shared__ alignas(16) float Ws[16][TN];
  float acc[8][TNI] = {};
  int t = threadIdx.x;               // 128 threads
  int tx = t & 7, ty = t >> 3;       // tx: n (0..7), ty: m (0..15)
  int wk[WPT], wn[WPT];
#pragma unroll
  for (int j = 0; j < WPT; j++) {
    int i = t + j * 128;
    wk[j] = i / TN;
    wn[j] = i - wk[j] * TN;
  }
  float4 pbv[4];
  float pw[WPT];
#define G2_LD(K0)                                                          \
  {                                                                        \
    _Pragma("unroll")                                                      \
    for (int jj = 0; jj < 4; jj++)                                         \
      pbv[jj] = *(const float4*)(Bg + (size_t)(m0 + t) * LDD + (K0) + jj * 4); \
    _Pragma("unroll")                                                      \
    for (int jj = 0; jj < WPT; jj++)                                       \
      pw[jj] = Wp[(size_t)((K0) + wk[jj]) * LDD + n0 + wn[jj]];            \
  }
  G2_LD(0);
  for (int k0 = 0; k0 < KK; k0 += 16) {
    __syncthreads();
#pragma unroll
    for (int jj = 0; jj < 4; jj++) {
      Bs[jj * 4 + 0][t] = pbv[jj].x;
      Bs[jj * 4 + 1][t] = pbv[jj].y;
      Bs[jj * 4 + 2][t] = pbv[jj].z;
      Bs[jj * 4 + 3][t] = pbv[jj].w;
    }
#pragma unroll
    for (int jj = 0; jj < WPT; jj++)
      Ws[wk[jj]][wn[jj]] = pw[jj];
    __syncthreads();
    if (k0 + 16 < KK) G2_LD(k0 + 16);
#pragma unroll
    for (int k = 0; k < 16; k++) {
      float a[8], b[TNI];
      *(float4*)&a[0] = *(float4*)&Bs[k][ty * 8];
      *(float4*)&a[4] = *(float4*)&Bs[k][ty * 8 + 4];
      if (TNI % 2 == 0) {
#pragma unroll
        for (int j = 0; j < TNI / 2; j++) {
          float2 vb = *(float2*)&Ws[k][tx * TNI + 2 * j];
          b[2 * j] = vb.x; b[2 * j + 1] = vb.y;
        }
      } else {
#pragma unroll
        for (int j = 0; j < TNI; j++) b[j] = Ws[k][tx * TNI + j];
      }
#pragma unroll
      for (int i = 0; i < 8; i++)
#pragma unroll
        for (int j = 0; j < TNI; j++)
          acc[i][j] += a[i] * b[j];
    }
  }
#undef G2_LD
  // epilogue: fold + crop + branch transpose, direct to output
  int rc[8], ra[8], rb[8], rcc[8];
#pragma unroll
  for (int i = 0; i < 8; i++) {
    int m = m0 + ty * 8 + i;
    int c = m / 1000;
    int rem = m - c * 1000;
    rc[i]  = c;
    ra[i]  = (rem / 100) * w0 - pb0;
    rb[i]  = ((rem / 10) % 10) * w1 - pb1;
    rcc[i] = (rem % 10) * w2 - pb2;
  }
  int cx[TNI], cy[TNI], cz[TNI]; bool cok[TNI];
#pragma unroll
  for (int j = 0; j < TNI; j++) {
    int col = n0 + tx * TNI + j;
    cok[j] = col < d;
    cx[j] = col / (w1 * w2);
    cy[j] = (col / w2) % w1;
    cz[j] = col % w2;
  }
#pragma unroll
  for (int i = 0; i < 8; i++) {
#pragma unroll
    for (int j = 0; j < TNI; j++) {
      if (cok[j]) {
        int u0 = ra[i] + cx[j];
        int u1 = rb[i] + cy[j];
        int u2 = rcc[i] + cz[j];
        if ((unsigned)u0 < (unsigned)s0 && (unsigned)u1 < (unsigned)s1 && (unsigned)u2 < (unsigned)s2) {
          long dst;
          if (BR == 0)      dst = ((long)(rc[i] * 48 + u0) * 66 + u1) * 38 + u2;
          else if (BR == 1) dst = ((long)(rc[i] * 38 + u0) * 66 + u2) * 38 + u1;
          else              dst = ((long)(rc[i] * 48 + u2) * 78 + u1) * 38 + u0;
          out[Tr<BR>::OFF + dst] = acc[i][j];
        }
      }
    }
  }
}

// single fused launch over (m-tiles, n-tiles, branch); TN = 48 / 56 / 56
__global__ void __launch_bounds__(128, 4) gemm2_all(float* __restrict__ out) {
  if (blockIdx.z == 0)      { gemm2_body<0, 48>(out); }
  else if (blockIdx.z == 1) { if (blockIdx.y < 2) gemm2_body<1, 56>(out); }
  else                      { gemm2_body<2, 56>(out); }
}

// ---------------- host driver ----------------
extern "C" void kernel_launch(void* const* d_in, const int* in_sizes, int n_in,
                              void* d_out, int out_size) {
  const float* axi   = (const float*)d_in[0];
  const float* cor   = (const float*)d_in[1];
  const float* sag   = (const float*)d_in[2];
  const float* atlas = (const float*)d_in[3];
  float* out = (float*)d_out;

  P3 pq = { (const float*)d_in[4],  (const float*)d_in[5],
            (const float*)d_in[10], (const float*)d_in[11],
            (const float*)d_in[16], (const float*)d_in[17] };
  P3 pk = { (const float*)d_in[6],  (const float*)d_in[7],
            (const float*)d_in[12], (const float*)d_in[13],
            (const float*)d_in[18], (const float*)d_in[19] };
  P3 pv = { (const float*)d_in[8],  (const float*)d_in[9],
            (const float*)d_in[14], (const float*)d_in[15],
            (const float*)d_in[20], (const float*)d_in[21] };

  // exact split-M: 64000 = 125*512 = 250*256 (no tail, unguarded loads)
  const int NS0 = 125, CH0 = 512;
  const int NS1 = 250, CH1 = 256;
  const int NS2 = 125, CH2 = 512;

  zero_all<<<(3 * GSTRIDE + 255) / 256, 256>>>();
  packB_all<<<dim3(6400, 3), 256>>>(axi, cor, sag);

  // gemm1 tile widths: br0 48 (3x3 covers 144>=141), br1 64 (2x2 covers 128>=113), br2 56 (3x3 covers 168>=161)
  packA_kernel<0><<<6400, 256>>>(atlas);
  gemm1_kernel<0, 48><<<dim3(3, 3, NS0), 64>>>(CH0);
  packA_kernel<1><<<6400, 256>>>(atlas);
  gemm1_kernel<1, 64><<<dim3(2, 2, NS1), 64>>>(CH1);
  packA_kernel<2><<<6400, 256>>>(atlas);
  gemm1_kernel<2, 56><<<dim3(3, 3, NS2), 64>>>(CH2);

  k3a_all<<<3 * 161, 192>>>(pk);
  k3b_all<<<3 * 160, 256>>>(pq);
  k3d_all<<<3 * 161, 192>>>(pv);

  gemm2_all<<<dim3(500, 3, 3), 128>>>(out);
}

// round 16
// speedup vs baseline: 1.8579x; 1.2580x over previous
#include <cuda_runtime.h>
#include <cstdint>

#define LDD 192
#define M_TOTAL 64000
#define AB_STRIDE ((size_t)M_TOTAL * LDD)
#define A0_LD 128
#define GSTRIDE (LDD * LDD)

// ---------------- scratch (static device globals) ----------------
static __device__ float g_B[3 * AB_STRIDE];   // ~147 MB (branch-batched)
static __device__ float g_A[(size_t)M_TOTAL * A0_LD];  // ~33 MB base atlas unfold (branch-shared)
static __device__ float g_G[3 * GSTRIDE];     // G0 per branch: 121 x D
static __device__ float g_T[3 * GSTRIDE];
static __device__ float g_Pt[3 * GSTRIDE];
static __device__ float g_Wp[3 * GSTRIDE];

// ---------------- per-branch compile-time traits ----------------
template<int BR> struct Tr;
template<> struct Tr<0> { // axi
  static constexpr int w0=5,w1=7,w2=4,d=140;
  static constexpr int s0=48,s1=66,s2=38;
  static constexpr int pb0=1,pb1=2,pb2=1;
  static constexpr long OFF=0;
};
template<> struct Tr<1> { // cor (internal transpose 0,1,2,4,3)
  static constexpr int w0=4,w1=4,w2=7,d=112;
  static constexpr int s0=38,s1=38,s2=66;
  static constexpr int pb0=1,pb1=1,pb2=2;
  static constexpr long OFF=7704576;
};
template<> struct Tr<2> { // sag (internal transpose 0,1,4,3,2)
  static constexpr int w0=4,w1=8,w2=5,d=160;
  static constexpr int s0=38,s1=78,s2=48;
  static constexpr int pb0=1,pb1=1,pb2=1;
  static constexpr long OFF=13804032;
};

// branch col -> base atlas unfold col (runtime version for k3a)
__device__ __forceinline__ int rowmap(int br, int r, int d) {
  if (r == d) return 120;  // ones column
  const int w1t[3] = {7, 4, 8}, w2t[3] = {4, 7, 5};
  int w1 = w1t[br], w2 = w2t[br];
  int x = r / (w1 * w2), y = (r / w2) % w1, z = r % w2;
  int xb, yb, zb;
  if (br == 0)      { xb = x; yb = (y * 6) / 7; zb = z; }
  else if (br == 1) { int x2=(x*5)/4, y2=(y*7)/4, z2=(z*4)/7; xb=x2; yb=(y2*6)/7; zb=z2; }
  else              { int y3=y/2, z3=(z*7)/5; int x2=(x*5)/4, y2=(y3*7)/4, z2=(z3*4)/7;
                      xb=x2; yb=(y2*6)/7; zb=z2; }
  return (xb * 6 + yb) * 4 + zb;
}

// ---------------- packB: gather B-hat (all branches) + zero G/Wp ----------------
template<int BR>
__device__ void packB_body(const float* __restrict__ feat) {
  constexpr int w0=Tr<BR>::w0, w1=Tr<BR>::w1, w2=Tr<BR>::w2, d=Tr<BR>::d;
  constexpr int s0=Tr<BR>::s0, s1=Tr<BR>::s1, s2=Tr<BR>::s2;
  constexpr int pb0=Tr<BR>::pb0, pb1=Tr<BR>::pb1, pb2=Tr<BR>::pb2;
  float* Bdst = g_B + (size_t)BR * AB_STRIDE;
  int blk = blockIdx.x;
  int c = blk / 100;
  int a = (blk / 10) % 10;
  int b = blk % 10;
  for (int t = threadIdx.x; t < 10 * LDD; t += blockDim.x) {
    int cc = t / LDD;
    int j  = t - cc * LDD;
    int row = blk * 10 + cc;
    float vB;
    if (j < d) {
      int x = j / (w1 * w2);
      int y = (j / w2) % w1;
      int z = j % w2;
      int i0 = a * w0 + x - pb0;
      int i1 = b * w1 + y - pb1;
      int i2 = cc * w2 + z - pb2;
      vB = 0.f;
      if ((unsigned)i0 < (unsigned)s0 && (unsigned)i1 < (unsigned)s1 && (unsigned)i2 < (unsigned)s2) {
        int src;
        if (BR == 0)      src = ((c * 48 + i0) * 66 + i1) * 38 + i2;
        else if (BR == 1) src = ((c * 38 + i0) * 66 + i2) * 38 + i1;
        else              src = ((c * 48 + i2) * 78 + i1) * 38 + i0;
        vB = feat[src];
      }
    } else {
      vB = (j == d) ? 1.f : 0.f;
    }
    Bdst[(size_t)row * LDD + j] = vB;
  }
}

__global__ void packB_all(const float* __restrict__ axi, const float* __restrict__ cor,
                          const float* __restrict__ sag) {
  // fused zero of G and Wp
  size_t gid = ((size_t)blockIdx.y * gridDim.x + blockIdx.x) * blockDim.x + threadIdx.x;
  if (gid < (size_t)3 * GSTRIDE) { g_G[gid] = 0.f; g_Wp[gid] = 0.f; }
  if (blockIdx.y == 0)      packB_body<0>(axi);
  else if (blockIdx.y == 1) packB_body<1>(cor);
  else                      packB_body<2>(sag);
}

// ---------------- packA0: base atlas unfold, ONCE for all branches ----------------
__global__ void packA0_kernel(const float* __restrict__ atlas) {
  int blk = blockIdx.x;
  int c = blk / 100;
  int a = (blk / 10) % 10;
  int b = blk % 10;
  for (int t = threadIdx.x; t < 10 * A0_LD; t += blockDim.x) {
    int cc = t / A0_LD;
    int j  = t - cc * A0_LD;
    int row = blk * 10 + cc;
    float vA;
    if (j < 120) {
      int x = j / 24;          // w = (5,6,4)
      int y = (j / 4) % 6;
      int z = j % 4;
      int j0 = a * 5 + x - 2;  // atlas aw=(5,6,4), pb=(2,2,1)
      int j1 = b * 6 + y - 2;
      int j2 = cc * 4 + z - 1;
      vA = 0.f;
      if ((unsigned)j0 < 46u && (unsigned)j1 < 56u && (unsigned)j2 < 38u)
        vA = atlas[((c * 46 + j0) * 56 + j1) * 38 + j2];
    } else {
      vA = (j == 120) ? 1.f : 0.f;
    }
    g_A[(size_t)row * A0_LD + j] = vA;
  }
}

// ---------------- GEMM1 (fused): G0 = A0^T B-hat, p-tile 64x2, q-tile TQ ----------------
template<int BR, int TQ>
__device__ __forceinline__ void g1body(int ms) {
  constexpr int QI = TQ / 8;
  int p0 = blockIdx.x * 64;
  int q0 = blockIdx.y * TQ;
  int m0 = ms * 512;
  int mHi = m0 + 512;
  const float* A  = g_A;
  const float* Bp = g_B + (size_t)BR * AB_STRIDE;
  float* G = g_G + BR * GSTRIDE;
  __shared__ alignas(16) float As[16][64];
  __shared__ alignas(16) float Bs[16][TQ];
  float acc[8][QI] = {};
  int t = threadIdx.x;               // 64 threads
  int tx = t & 7, ty = t >> 3;
  int lr = t >> 2;                   // 16 rows
  int lp = t & 3;                    // 4 threads per row
  float4 pa[4];
  float2 pb[QI];
#define G1_LD(MB)                                                          \
  {                                                                        \
    const float* ar  = A  + (size_t)((MB) + lr) * A0_LD + p0;              \
    const float* brr = Bp + (size_t)((MB) + lr) * LDD + q0;                \
    _Pragma("unroll")                                                      \
    for (int i = 0; i < 4; i++)  pa[i] = *(const float4*)(ar + lp * 16 + i * 4); \
    _Pragma("unroll")                                                      \
    for (int i = 0; i < QI; i++) pb[i] = *(const float2*)(brr + (lp * QI + i) * 2); \
  }
  G1_LD(m0);
  for (int mb = m0; mb < mHi; mb += 16) {
    __syncthreads();
#pragma unroll
    for (int i = 0; i < 4; i++)  *(float4*)&As[lr][lp * 16 + i * 4] = pa[i];
#pragma unroll
    for (int i = 0; i < QI; i++) *(float2*)&Bs[lr][(lp * QI + i) * 2] = pb[i];
    __syncthreads();
    if (mb + 16 < mHi) G1_LD(mb + 16);
#pragma unroll
    for (int k = 0; k < 16; k++) {
      float a[8], b[QI];
      *(float4*)&a[0] = *(float4*)&As[k][ty * 8];
      *(float4*)&a[4] = *(float4*)&As[k][ty * 8 + 4];
      if (QI % 2 == 0) {
#pragma unroll
        for (int j = 0; j < QI / 2; j++) {
          float2 vb = *(float2*)&Bs[k][tx * QI + 2 * j];
          b[2 * j] = vb.x; b[2 * j + 1] = vb.y;
        }
      } else {
#pragma unroll
        for (int j = 0; j < QI; j++) b[j] = Bs[k][tx * QI + j];
      }
#pragma unroll
      for (int i = 0; i < 8; i++)
#pragma unroll
        for (int j = 0; j < QI; j++)
          acc[i][j] += a[i] * b[j];
    }
  }
#pragma unroll
  for (int i = 0; i < 8; i++)
#pragma unroll
    for (int j = 0; j < QI; j++)
      atomicAdd(&G[(p0 + ty * 8 + i) * LDD + q0 + tx * QI + j], acc[i][j]);
#undef G1_LD
}

// grid: x=2 (p tiles of 64 covering 121), y=3 (q tiles; br1 masks y<2), z=375 (branch*125 + split)
__global__ void __launch_bounds__(64, 8) gemm1_all() {
  int z = blockIdx.z;
  int br = z / 125;
  int ms = z - br * 125;
  if (br == 0)      { g1body<0, 48>(ms); }
  else if (br == 1) { if (blockIdx.y < 2) g1body<1, 64>(ms); }
  else              { g1body<2, 56>(ms); }
}

// ---------------- small chain (batched across branches) ----------------
struct P3 { const float* W0; const float* b0; const float* W1; const float* b1;
            const float* W2; const float* b2; };

__device__ __forceinline__ void sel(const P3& p, int br, const float*& W, const float*& b) {
  if (br == 0)      { W = p.W0; b = p.b0; }
  else if (br == 1) { W = p.W1; b = p.b1; }
  else              { W = p.W2; b = p.b2; }
}

// T = G-hat @ Wk-hat  (row r of G-hat = row rowmap(r) of G0)
__global__ void k3a_all(P3 pk) {
  const int dTab[3] = {140, 112, 160};
  int br = blockIdx.x / 161;
  int r  = blockIdx.x - br * 161;
  int d = dTab[br];
  if (r > d) return;
  const float *Wk, *bk; sel(pk, br, Wk, bk);
  const float* G = g_G + br * GSTRIDE;
  float* T = g_T + br * GSTRIDE;
  __shared__ float gsh[192];
  int t = threadIdx.x;               // 192
  int base = rowmap(br, r, d);
  gsh[t] = (t <= d) ? G[base * LDD + t] : 0.f;
  __syncthreads();
  if (t < d) {
    float s = gsh[d] * bk[t];
#pragma unroll 4
    for (int ss = 0; ss < d; ss++) s += gsh[ss] * Wk[ss * d + t];
    T[r * LDD + t] = s;
  }
}

// S row p = Wq-hat[:,p]^T @ T, fused softmax, write P transposed
__global__ void k3b_all(P3 pq) {
  const int dTab[3] = {140, 112, 160};
  int br = blockIdx.x / 160;
  int p  = blockIdx.x - br * 160;
  int d = dTab[br];
  if (p >= d) return;
  const float *Wq, *bq; sel(pq, br, Wq, bq);
  const float* T = g_T + br * GSTRIDE;
  float* Pt = g_Pt + br * GSTRIDE;
  __shared__ float wq[192];
  __shared__ float red[256];
  int t = threadIdx.x;               // 256
  int D = d + 1;
  if (t < 192) wq[t] = (t < d) ? Wq[t * d + p] : ((t == d) ? bq[p] : 0.f);
  __syncthreads();
  float s = -3.0e38f;
  if (t < d) {
    s = 0.f;
#pragma unroll 4
    for (int r = 0; r < D; r++) s += wq[r] * T[r * LDD + t];
  }
  red[t] = s; __syncthreads();
  for (int o = 128; o > 0; o >>= 1) { if (t < o) red[t] = fmaxf(red[t], red[t + o]); __syncthreads(); }
  float mx = red[0]; __syncthreads();
  float e = (t < d) ? expf(s - mx) : 0.f;
  red[t] = e; __syncthreads();
  for (int o = 128; o > 0; o >>= 1) { if (t < o) red[t] += red[t + o]; __syncthreads(); }
  float inv = 1.f / red[0];
  if (t < d) Pt[t * LDD + p] = e * inv;
}

// W' row j = Wv-hat[j,:] @ P^T
__global__ void k3d_all(P3 pv) {
  const int dTab[3] = {140, 112, 160};
  int br = blockIdx.x / 161;
  int j  = blockIdx.x - br * 161;
  int d = dTab[br];
  if (j > d) return;
  const float *Wv, *bv; sel(pv, br, Wv, bv);
  const float* Pt = g_Pt + br * GSTRIDE;
  float* Wp = g_Wp + br * GSTRIDE;
  __shared__ float wv[192];
  int t = threadIdx.x;               // 192
  if (t < d) wv[t] = (j < d) ? Wv[j * d + t] : bv[t];
  __syncthreads();
  if (t < d) {
    float s = 0.f;
#pragma unroll 4
    for (int l = 0; l < d; l++) s += wv[l] * Pt[l * LDD + t];
    Wp[j * LDD + t] = s;
  }
}

// ---------------- GEMM2: cross = B-hat @ W', 128 x TN tile (TN=48/56/56), fused scatter ----------------
template<int BR, int TN>
__device__ __forceinline__ void gemm2_body(float* __restrict__ out) {
  constexpr int d  = Tr<BR>::d;
  constexpr int w0 = Tr<BR>::w0, w1 = Tr<BR>::w1, w2 = Tr<BR>::w2;
  constexpr int s0 = Tr<BR>::s0, s1 = Tr<BR>::s1, s2 = Tr<BR>::s2;
  constexpr int pb0 = Tr<BR>::pb0, pb1 = Tr<BR>::pb1, pb2 = Tr<BR>::pb2;
  constexpr int KK = ((d + 1 + 15) / 16) * 16;
  constexpr int TNI = TN / 8;
  constexpr int WPT = (16 * TN) / 128;
  int m0 = blockIdx.x * 128;
  int n0 = blockIdx.y * TN;
  const float* Bg = g_B + (size_t)BR * AB_STRIDE;
  const float* Wp = g_Wp + BR * GSTRIDE;
  __shared__ alignas(16) float Bs[16][128];    // transposed: Bs[k][m]
  __shared__ alignas(16) float Ws[16][TN];
  float acc[8][TNI] = {};
  int t = threadIdx.x;               // 128 threads
  int tx = t & 7, ty = t >> 3;
  int wk[WPT], wn[WPT];
#pragma unroll
  for (int j = 0; j < WPT; j++) {
    int i = t + j * 128;
    wk[j] = i / TN;
    wn[j] = i - wk[j] * TN;
  }
  float4 pbv[4];
  float pw[WPT];
#define G2_LD(K0)                                                          \
  {                                                                        \
    _Pragma("unroll")                                                      \
    for (int jj = 0; jj < 4; jj++)                                         \
      pbv[jj] = *(const float4*)(Bg + (size_t)(m0 + t) * LDD + (K0) + jj * 4); \
    _Pragma("unroll")                                                      \
    for (int jj = 0; jj < WPT; jj++)                                       \
      pw[jj] = Wp[(size_t)((K0) + wk[jj]) * LDD + n0 + wn[jj]];            \
  }
  G2_LD(0);
  for (int k0 = 0; k0 < KK; k0 += 16) {
    __syncthreads();
#pragma unroll
    for (int jj = 0; jj < 4; jj++) {
      Bs[jj * 4 + 0][t] = pbv[jj].x;
      Bs[jj * 4 + 1][t] = pbv[jj].y;
      Bs[jj * 4 + 2][t] = pbv[jj].z;
      Bs[jj * 4 + 3][t] = pbv[jj].w;
    }
#pragma unroll
    for (int jj = 0; jj < WPT; jj++)
      Ws[wk[jj]][wn[jj]] = pw[jj];
    __syncthreads();
    if (k0 + 16 < KK) G2_LD(k0 + 16);
#pragma unroll
    for (int k = 0; k < 16; k++) {
      float a[8], b[TNI];
      *(float4*)&a[0] = *(float4*)&Bs[k][ty * 8];
      *(float4*)&a[4] = *(float4*)&Bs[k][ty * 8 + 4];
      if (TNI % 2 == 0) {
#pragma unroll
        for (int j = 0; j < TNI / 2; j++) {
          float2 vb = *(float2*)&Ws[k][tx * TNI + 2 * j];
          b[2 * j] = vb.x; b[2 * j + 1] = vb.y;
        }
      } else {
#pragma unroll
        for (int j = 0; j < TNI; j++) b[j] = Ws[k][tx * TNI + j];
      }
#pragma unroll
      for (int i = 0; i < 8; i++)
#pragma unroll
        for (int j = 0; j < TNI; j++)
          acc[i][j] += a[i] * b[j];
    }
  }
#undef G2_LD
  int rc[8], ra[8], rb[8], rcc[8];
#pragma unroll
  for (int i = 0; i < 8; i++) {
    int m = m0 + ty * 8 + i;
    int c = m / 1000;
    int rem = m - c * 1000;
    rc[i]  = c;
    ra[i]  = (rem / 100) * w0 - pb0;
    rb[i]  = ((rem / 10) % 10) * w1 - pb1;
    rcc[i] = (rem % 10) * w2 - pb2;
  }
  int cx[TNI], cy[TNI], cz[TNI]; bool cok[TNI];
#pragma unroll
  for (int j = 0; j < TNI; j++) {
    int col = n0 + tx * TNI + j;
    cok[j] = col < d;
    cx[j] = col / (w1 * w2);
    cy[j] = (col / w2) % w1;
    cz[j] = col % w2;
  }
#pragma unroll
  for (int i = 0; i < 8; i++) {
#pragma unroll
    for (int j = 0; j < TNI; j++) {
      if (cok[j]) {
        int u0 = ra[i] + cx[j];
        int u1 = rb[i] + cy[j];
        int u2 = rcc[i] + cz[j];
        if ((unsigned)u0 < (unsigned)s0 && (unsigned)u1 < (unsigned)s1 && (unsigned)u2 < (unsigned)s2) {
          long dst;
          if (BR == 0)      dst = ((long)(rc[i] * 48 + u0) * 66 + u1) * 38 + u2;
          else if (BR == 1) dst = ((long)(rc[i] * 38 + u0) * 66 + u2) * 38 + u1;
          else              dst = ((long)(rc[i] * 48 + u2) * 78 + u1) * 38 + u0;
          out[Tr<BR>::OFF + dst] = acc[i][j];
        }
      }
    }
  }
}

__global__ void __launch_bounds__(128, 4) gemm2_all(float* __restrict__ out) {
  if (blockIdx.z == 0)      { gemm2_body<0, 48>(out); }
  else if (blockIdx.z == 1) { if (blockIdx.y < 2) gemm2_body<1, 56>(out); }
  else                      { gemm2_body<2, 56>(out); }
}

// ---------------- host driver ----------------
extern "C" void kernel_launch(void* const* d_in, const int* in_sizes, int n_in,
                              void* d_out, int out_size) {
  const float* axi   = (const float*)d_in[0];
  const float* cor   = (const float*)d_in[1];
  const float* sag   = (const float*)d_in[2];
  const float* atlas = (const float*)d_in[3];
  float* out = (float*)d_out;

  P3 pq = { (const float*)d_in[4],  (const float*)d_in[5],
            (const float*)d_in[10], (const float*)d_in[11],
            (const float*)d_in[16], (const float*)d_in[17] };
  P3 pk = { (const float*)d_in[6],  (const float*)d_in[7],
            (const float*)d_in[12], (const float*)d_in[13],
            (const float*)d_in[18], (const float*)d_in[19] };
  P3 pv = { (const float*)d_in[8],  (const float*)d_in[9],
            (const float*)d_in[14], (const float*)d_in[15],
            (const float*)d_in[20], (const float*)d_in[21] };

  packB_all<<<dim3(6400, 3), 256>>>(axi, cor, sag);      // includes G/Wp zeroing
  packA0_kernel<<<6400, 256>>>(atlas);
  gemm1_all<<<dim3(2, 3, 375), 64>>>();
  k3a_all<<<3 * 161, 192>>>(pk);
  k3b_all<<<3 * 160, 256>>>(pq);
  k3d_all<<<3 * 161, 192>>>(pv);
  gemm2_all<<<dim3(500, 3, 3), 128>>>(out);
}